// round 7
// baseline (speedup 1.0000x reference)
#include <cuda_runtime.h>
#include <cuda_bf16.h>
#include <math.h>
#include <stdint.h>

#define Bz   64
#define Sz   32
#define NF   196
#define NP   64
#define ENC  512
#define BENC 768
#define Az   512
#define Dz   512
#define Ez   512
#define Vz   30000
#define G4   2048
#define VPAD 30208
#define NBLK 128

#define OFF_ALPHA  61440000u
#define OFF_PA     61841408u

// ---------------- scratch ----------------
__device__ float g_u_feat[Bz * NF * Az];
__device__ float g_u_art [Bz * NP * Az];
__device__ float g_h[Bz * Dz], g_c[Bz * Dz];
__device__ float g_ctx[Bz * ENC], g_pctx[Bz * BENC];
__device__ float g_embs[Bz * Sz * Ez];
__device__ float g_gparts[4 * Bz * G4];
__device__ float g_wah[2 * Bz * Az];

__device__ __nv_bfloat16 g_fhi[Bz * NF * ENC],  g_flo[Bz * NF * ENC];
__device__ __nv_bfloat16 g_arhi[Bz * NP * BENC], g_arlo[Bz * NP * BENC];
__device__ __nv_bfloat16 g_w1hi[Az * ENC],  g_w1lo[Az * ENC];
__device__ __nv_bfloat16 g_w2hi[Az * BENC], g_w2lo[Az * BENC];
__device__ __nv_bfloat16 g_whi[(size_t)VPAD * Dz], g_wlo[(size_t)VPAD * Dz];
__device__ __nv_bfloat16 g_ahi[Sz * Bz * Dz], g_alo[Sz * Bz * Dz];

__device__ unsigned g_cnt;
__device__ volatile unsigned g_gen;

__device__ __forceinline__ float wred(float v) {
#pragma unroll
    for (int o = 16; o; o >>= 1) v += __shfl_xor_sync(0xffffffffu, v, o);
    return v;
}
__device__ __forceinline__ float sigm(float x) { return 1.f / (1.f + expf(-x)); }
__device__ __forceinline__ float tanha(float x) {
    float y; asm("tanh.approx.f32 %0, %1;" : "=f"(y) : "f"(x)); return y;
}
__device__ __forceinline__ uint32_t smem_u32(const void* p) {
    uint32_t a;
    asm("{ .reg .u64 t; cvta.to.shared.u64 t, %1; cvt.u32.u64 %0, t; }" : "=r"(a) : "l"(p));
    return a;
}
__device__ __forceinline__ void mma16816(float* c, uint32_t a0, uint32_t a1, uint32_t a2,
                                         uint32_t a3, uint32_t b0, uint32_t b1) {
    asm("mma.sync.aligned.m16n8k16.row.col.f32.bf16.bf16.f32 "
        "{%0,%1,%2,%3}, {%4,%5,%6,%7}, {%8,%9}, {%0,%1,%2,%3};"
        : "+f"(c[0]), "+f"(c[1]), "+f"(c[2]), "+f"(c[3])
        : "r"(a0), "r"(a1), "r"(a2), "r"(a3), "r"(b0), "r"(b1));
}
__device__ __forceinline__ uint32_t swz(int r, int slot) {
    return (uint32_t)(r * 64 + ((slot ^ ((r >> 1) & 3)) << 4));
}
__device__ __forceinline__ void cpa16(uint32_t dst, const void* src) {
    asm volatile("cp.async.cg.shared.global [%0], [%1], 16;" :: "r"(dst), "l"(src));
}

__device__ __forceinline__ void gbar() {
    __threadfence();
    __syncthreads();
    if (threadIdx.x == 0) {
        unsigned gen = g_gen;
        if (atomicAdd(&g_cnt, 1u) == NBLK - 1) {
            g_cnt = 0;
            __threadfence();
            g_gen = gen + 1;
        } else {
            while (g_gen == gen) {}
        }
    }
    __syncthreads();
}

// ---------------- mega prologue ----------------
__device__ __forceinline__ void conv_range(const float* __restrict__ src,
                                           __nv_bfloat16* __restrict__ hi,
                                           __nv_bfloat16* __restrict__ lo,
                                           int n_src, int relblk) {
    int i = (relblk * 256 + threadIdx.x) * 4;
    float4 v = make_float4(0.f, 0.f, 0.f, 0.f);
    if (i < n_src) v = *(const float4*)(src + i);
    __nv_bfloat16 h0 = __float2bfloat16(v.x), h1 = __float2bfloat16(v.y);
    __nv_bfloat16 h2 = __float2bfloat16(v.z), h3 = __float2bfloat16(v.w);
    ((__nv_bfloat162*)(hi + i))[0] = __halves2bfloat162(h0, h1);
    ((__nv_bfloat162*)(hi + i))[1] = __halves2bfloat162(h2, h3);
    ((__nv_bfloat162*)(lo + i))[0] = __halves2bfloat162(
        __float2bfloat16(v.x - __bfloat162float(h0)), __float2bfloat16(v.y - __bfloat162float(h1)));
    ((__nv_bfloat162*)(lo + i))[1] = __halves2bfloat162(
        __float2bfloat16(v.z - __bfloat162float(h2)), __float2bfloat16(v.w - __bfloat162float(h3)));
}

#define PB_MEAN   0
#define PB_EMBED  64
#define PB_CF     2112
#define PB_CAR    8384
#define PB_CW1    11456
#define PB_CW2    11712
#define PB_CWF    12096
#define PB_TOTAL  27200

__global__ void prologue(const float* __restrict__ features, const float* __restrict__ articles,
                         const float* __restrict__ emb, const int* __restrict__ captions,
                         const float* __restrict__ ihw, const float* __restrict__ ihb,
                         const float* __restrict__ icw, const float* __restrict__ icb,
                         const float* __restrict__ attUw, const float* __restrict__ paUw,
                         const float* __restrict__ fcnw) {
    int blk = blockIdx.x, tid = threadIdx.x;
    if (blk < PB_EMBED) {
        // mean pooling + init h0/c0 for batch b
        __shared__ float x[1280];
        int b = blk, lane = tid & 31, wid = tid >> 5;
        for (int k = tid; k < ENC; k += 256) {
            float s = 0.f;
            const float* p = features + (size_t)b * NF * ENC + k;
            for (int n = 0; n < NF; n++) s += p[n * ENC];
            x[k] = s * (1.f / NF);
        }
        for (int k = tid; k < BENC; k += 256) {
            float s = 0.f;
            const float* p = articles + (size_t)b * NP * BENC + k;
            for (int n = 0; n < NP; n++) s += p[n * BENC];
            x[ENC + k] = s * (1.f / NP);
        }
        __syncthreads();
        for (int d = wid; d < Dz; d += 8) {
            float sh = 0.f, sc = 0.f;
            const float* hr = ihw + (size_t)d * 1280;
            const float* cr = icw + (size_t)d * 1280;
            for (int k = lane; k < 1280; k += 32) { float xv = x[k]; sh += hr[k] * xv; sc += cr[k] * xv; }
#pragma unroll
            for (int o = 16; o; o >>= 1) {
                sh += __shfl_xor_sync(0xffffffffu, sh, o);
                sc += __shfl_xor_sync(0xffffffffu, sc, o);
            }
            if (!lane) { g_h[b * Dz + d] = sh + ihb[d]; g_c[b * Dz + d] = sc + icb[d]; }
        }
    } else if (blk < PB_CF) {
        int bs = blk - PB_EMBED;
        int cap = captions[bs];
        const float* e = emb + (size_t)cap * Ez;
        for (int k = tid; k < Ez; k += 256) g_embs[(size_t)bs * Ez + k] = e[k];
    } else if (blk < PB_CAR) {
        conv_range(features, g_fhi, g_flo, Bz * NF * ENC, blk - PB_CF);
    } else if (blk < PB_CW1) {
        conv_range(articles, g_arhi, g_arlo, Bz * NP * BENC, blk - PB_CAR);
    } else if (blk < PB_CW2) {
        conv_range(attUw, g_w1hi, g_w1lo, Az * ENC, blk - PB_CW1);
    } else if (blk < PB_CWF) {
        conv_range(paUw, g_w2hi, g_w2lo, Az * BENC, blk - PB_CW2);
    } else {
        conv_range(fcnw, g_whi, g_wlo, Vz * Dz, blk - PB_CWF);
    }
}

// -------- split-bf16 mma.sync GEMM, cp.async double-buffered --------
template <bool PERM>
__global__ void __launch_bounds__(256)
gemm_mma(const __nv_bfloat16* __restrict__ Ahi, const __nv_bfloat16* __restrict__ Alo,
         const __nv_bfloat16* __restrict__ Whi, const __nv_bfloat16* __restrict__ Wlo,
         const float* __restrict__ bias, float* __restrict__ C, int N, int K) {
    __shared__ __align__(16) char smA[2][8192];
    __shared__ __align__(16) char smW[2][8192];
    const int tid = threadIdx.x, lane = tid & 31, wid = tid >> 5;
    const int wm = wid & 1, wn = wid >> 1;
    const int lr4 = lane >> 2, lw = lane & 3;
    const int n0 = blockIdx.x * 128, m0 = blockIdx.y * 128;
    const int kc = K >> 5, nch = 3 * kc;
    const int r1 = tid >> 2, cA = tid & 3;
    const uint32_t so1 = swz(r1, cA), so2 = swz(r1 + 64, cA);
    const uint32_t sa[2] = { smem_u32(smA[0]), smem_u32(smA[1]) };
    const uint32_t sb[2] = { smem_u32(smW[0]), smem_u32(smW[1]) };

    float acc[4][4][4] = {};

#define ISSUE(cc, st) do {                                                     \
        int part = ((cc) >= 2 * kc) ? 2 : ((cc) >= kc ? 1 : 0);                \
        int kk = ((cc) - part * kc) << 5;                                      \
        const __nv_bfloat16* As = (part == 1) ? Alo : Ahi;                     \
        const __nv_bfloat16* Ws = (part == 2) ? Wlo : Whi;                     \
        cpa16(sa[st] + so1, As + (size_t)(m0 + r1) * K + kk + cA * 8);         \
        cpa16(sa[st] + so2, As + (size_t)(m0 + r1 + 64) * K + kk + cA * 8);    \
        cpa16(sb[st] + so1, Ws + (size_t)(n0 + r1) * K + kk + cA * 8);         \
        cpa16(sb[st] + so2, Ws + (size_t)(n0 + r1 + 64) * K + kk + cA * 8);    \
        asm volatile("cp.async.commit_group;" ::: "memory");                   \
    } while (0)

    ISSUE(0, 0);
    for (int cc = 0; cc < nch; cc++) {
        const int st = cc & 1;
        if (cc + 1 < nch) {
            ISSUE(cc + 1, st ^ 1);
            asm volatile("cp.async.wait_group 1;" ::: "memory");
        } else {
            asm volatile("cp.async.wait_group 0;" ::: "memory");
        }
        __syncthreads();
        const char* pA = smA[st];
        const char* pW = smW[st];
#pragma unroll
        for (int ks = 0; ks < 2; ks++) {
            uint32_t bf[4][2];
#pragma unroll
            for (int ni = 0; ni < 4; ni++) {
                int nb = wn * 32 + ni * 8 + lr4;
                bf[ni][0] = *(const uint32_t*)(pW + swz(nb, 2 * ks) + lw * 4);
                bf[ni][1] = *(const uint32_t*)(pW + swz(nb, 2 * ks + 1) + lw * 4);
            }
#pragma unroll
            for (int mi = 0; mi < 4; mi++) {
                int ra = wm * 64 + mi * 16 + lr4, rb = ra + 8;
                uint32_t a0 = *(const uint32_t*)(pA + swz(ra, 2 * ks) + lw * 4);
                uint32_t a1 = *(const uint32_t*)(pA + swz(rb, 2 * ks) + lw * 4);
                uint32_t a2 = *(const uint32_t*)(pA + swz(ra, 2 * ks + 1) + lw * 4);
                uint32_t a3 = *(const uint32_t*)(pA + swz(rb, 2 * ks + 1) + lw * 4);
#pragma unroll
                for (int ni = 0; ni < 4; ni++)
                    mma16816(acc[mi][ni], a0, a1, a2, a3, bf[ni][0], bf[ni][1]);
            }
        }
        __syncthreads();
    }
#undef ISSUE

#pragma unroll
    for (int mi = 0; mi < 4; mi++) {
#pragma unroll
        for (int ni = 0; ni < 4; ni++) {
            int m = m0 + wm * 64 + mi * 16 + lr4;
            int n = n0 + wn * 32 + ni * 8 + lw * 2;
            if (n < N) {
                float bx = bias[n], by = bias[n + 1];
                size_t row0 = PERM ? (size_t)((m & 63) * Sz + (m >> 6)) * N : (size_t)m * N;
                size_t row1 = PERM ? (size_t)(((m + 8) & 63) * Sz + ((m + 8) >> 6)) * N
                                   : (size_t)(m + 8) * N;
                *(float2*)(C + row0 + n) = make_float2(acc[mi][ni][0] + bx, acc[mi][ni][1] + by);
                *(float2*)(C + row1 + n) = make_float2(acc[mi][ni][2] + bx, acc[mi][ni][3] + by);
            }
        }
    }
}

// ---------------- persistent loop pieces ----------------
__device__ __forceinline__ void wah_phase(float* sh, const float* __restrict__ Ww,
                                          const float* __restrict__ Wb, int type, int slice) {
    const int tid = threadIdx.x, lane = tid & 31, w = tid >> 5;
    float* sW = sh;          // 4096
    float* swb = sh + 4096;  // 8
    const int a0 = slice * 8;
    for (int i = tid; i < 4096; i += 256)
        sW[i] = Ww[(size_t)(a0 + (i >> 9)) * Dz + (i & 511)];
    if (tid < 8) swb[tid] = Wb[a0 + tid];
    __syncthreads();
#pragma unroll 1
    for (int bb = 0; bb < 8; bb++) {
        int b = w * 8 + bb;
        float hreg[16];
        const float* hp = g_h + b * Dz + lane;
#pragma unroll
        for (int q = 0; q < 16; q++) hreg[q] = hp[q * 32];
#pragma unroll 1
        for (int ap = 0; ap < 8; ap++) {
            const float* wr = sW + ap * 512 + lane;
            float s = 0.f;
#pragma unroll
            for (int q = 0; q < 16; q++) s += wr[q * 32] * hreg[q];
            s = wred(s);
            if (!lane) g_wah[(size_t)(type * Bz + b) * Az + a0 + ap] = s + swb[ap];
        }
    }
    __syncthreads();
}

__device__ __forceinline__ void attend_p(float* sh, const float* __restrict__ F,
                                         const float* __restrict__ u,
                                         const float* __restrict__ Aw, float Ab,
                                         int type, int b, int Nn, int Kd,
                                         float* __restrict__ ctxp, float* __restrict__ outp) {
    const int tid = threadIdx.x, lane = tid & 31, wid = tid >> 5;
    float* wahs = sh;         // 512
    float* sc   = sh + 512;   // 200
    float* red  = sh + 720;   // 8
    float* sm   = sh + 728;   // 2

    wahs[tid] = g_wah[(size_t)(type * Bz + b) * Az + tid];
    wahs[tid + 256] = g_wah[(size_t)(type * Bz + b) * Az + tid + 256];
    __syncthreads();

    for (int n = wid; n < Nn; n += 8) {
        const float* ur = u + (size_t)n * Az;
        float s = 0.f;
        for (int a = lane; a < Az; a += 32) s += tanha(ur[a] + wahs[a]) * Aw[a];
        s = wred(s);
        if (!lane) sc[n] = s + Ab;
    }
    __syncthreads();

    float m = -1e30f;
    for (int n = tid; n < Nn; n += 256) m = fmaxf(m, sc[n]);
#pragma unroll
    for (int o = 16; o; o >>= 1) m = fmaxf(m, __shfl_xor_sync(0xffffffffu, m, o));
    if (!lane) red[wid] = m;
    __syncthreads();
    if (tid == 0) {
        float mm = red[0];
        for (int i = 1; i < 8; i++) mm = fmaxf(mm, red[i]);
        sm[0] = mm;
    }
    __syncthreads();
    float e = 0.f;
    for (int n = tid; n < Nn; n += 256) { float ex = expf(sc[n] - sm[0]); sc[n] = ex; e += ex; }
    e = wred(e);
    if (!lane) red[wid] = e;
    __syncthreads();
    if (tid == 0) {
        float ss = 0.f;
        for (int i = 0; i < 8; i++) ss += red[i];
        sm[1] = ss;
    }
    __syncthreads();
    const float inv = 1.f / sm[1];
    for (int n = tid; n < Nn; n += 256) { float al = sc[n] * inv; sc[n] = al; outp[n] = al; }
    __syncthreads();

    for (int k = tid; k < Kd; k += 256) {
        float acc = 0.f;
        for (int n = 0; n < Nn; n++) acc += sc[n] * F[(size_t)n * Kd + k];
        ctxp[k] = acc;
    }
}

__device__ __forceinline__ void gates_p(float* sh, const float* __restrict__ w_ih,
                                        const float* __restrict__ w_hh, int s, int n0, int t) {
    float* Xs = sh;            // [16][64]
    float* Ws = sh + 1024;     // [16][32]
    const int tid = threadIdx.x;
    const int tx = tid % 8, ty = tid / 8;
    const int xr = tid / 4, xc = (tid % 4) * 4;

    const float* xs;
    int Ks, kofs;
    if (s == 0)      { xs = g_embs + ((size_t)xr * Sz + t) * Ez; Ks = 512; kofs = 0; }
    else if (s == 1) { xs = g_ctx + xr * ENC;   Ks = 512; kofs = 512; }
    else if (s == 2) { xs = g_pctx + xr * BENC; Ks = 768; kofs = 1024; }
    else             { xs = g_h + xr * Dz;      Ks = 512; kofs = 0; }

    const int iters = Ks / 16;
    float acc[2][4] = {};
    __syncthreads();
    for (int it = 0; it < iters; it++) {
        int kl = it * 16;
        float4 xv = *(const float4*)&xs[kl + xc];
        float4 wv = make_float4(0.f, 0.f, 0.f, 0.f);
        if (tid < 128) {
            int j = n0 + tid / 4;
            int kg = kl + (tid % 4) * 4;
            const float* src = (s == 3) ? &w_hh[(size_t)j * 512 + kg]
                                        : &w_ih[(size_t)j * 1792 + kofs + kg];
            wv = *(const float4*)src;
        }
        __syncthreads();
        Xs[(xc + 0) * 64 + xr] = xv.x; Xs[(xc + 1) * 64 + xr] = xv.y;
        Xs[(xc + 2) * 64 + xr] = xv.z; Xs[(xc + 3) * 64 + xr] = xv.w;
        if (tid < 128) {
            int n = tid / 4, kq = (tid % 4) * 4;
            Ws[(kq + 0) * 32 + n] = wv.x; Ws[(kq + 1) * 32 + n] = wv.y;
            Ws[(kq + 2) * 32 + n] = wv.z; Ws[(kq + 3) * 32 + n] = wv.w;
        }
        __syncthreads();
#pragma unroll
        for (int k = 0; k < 16; k++) {
            float ra0 = Xs[k * 64 + ty * 2], ra1 = Xs[k * 64 + ty * 2 + 1];
            float rb[4];
            *(float4*)&rb[0] = *(const float4*)&Ws[k * 32 + tx * 4];
#pragma unroll
            for (int j = 0; j < 4; j++) { acc[0][j] += ra0 * rb[j]; acc[1][j] += ra1 * rb[j]; }
        }
        __syncthreads();
    }
#pragma unroll
    for (int i = 0; i < 2; i++) {
        int b = ty * 2 + i;
#pragma unroll
        for (int j = 0; j < 4; j++)
            g_gparts[((size_t)s * Bz + b) * G4 + n0 + tx * 4 + j] = acc[i][j];
    }
}

__global__ void __launch_bounds__(256)
loop_kernel(const float* __restrict__ features, const float* __restrict__ articles,
            const float* __restrict__ attWw, const float* __restrict__ attWb,
            const float* __restrict__ attAw, const float* __restrict__ attAb,
            const float* __restrict__ paWw, const float* __restrict__ paWb,
            const float* __restrict__ paAw, const float* __restrict__ paAb,
            const float* __restrict__ w_ih, const float* __restrict__ w_hh,
            const float* __restrict__ b_ih, const float* __restrict__ b_hh,
            float* __restrict__ out) {
    __shared__ float sh[4352];
    const int bid = blockIdx.x, tid = threadIdx.x;
    const int type = bid >> 6, b = bid & 63;

    for (int t = 0; t < Sz; t++) {
        // A: batched wah slices + h-independent gate segments
        wah_phase(sh, type ? paWw : attWw, type ? paWb : attWb, type, b);
        gates_p(sh, w_ih, w_hh, type ? 3 : 0, b * 32, t);
        gbar();
        // B: attention (scores, softmax, alphas out, ctx)
        if (type == 0)
            attend_p(sh, features + (size_t)b * NF * ENC, g_u_feat + (size_t)b * NF * Az,
                     attAw, attAb[0], 0, b, NF, ENC, g_ctx + b * ENC,
                     out + OFF_ALPHA + (size_t)(b * Sz + t) * NF);
        else
            attend_p(sh, articles + (size_t)b * NP * BENC, g_u_art + (size_t)b * NP * Az,
                     paAw, paAb[0], 1, b, NP, BENC, g_pctx + b * BENC,
                     out + OFF_PA + (size_t)(b * Sz + t) * NP);
        gbar();
        // C: ctx-dependent gate segments
        gates_p(sh, w_ih, w_hh, type ? 2 : 1, b * 32, t);
        gbar();
        // D: LSTM pointwise
        if (type == 0) {
            for (int d = tid; d < Dz; d += 256) {
                float gi = b_ih[d] + b_hh[d];
                float gf = b_ih[512 + d] + b_hh[512 + d];
                float gg = b_ih[1024 + d] + b_hh[1024 + d];
                float go = b_ih[1536 + d] + b_hh[1536 + d];
#pragma unroll
                for (int ks = 0; ks < 4; ks++) {
                    const float* gp = g_gparts + ((size_t)ks * Bz + b) * G4;
                    gi += gp[d]; gf += gp[512 + d]; gg += gp[1024 + d]; go += gp[1536 + d];
                }
                float cp = g_c[b * Dz + d];
                float cn = sigm(gf) * cp + sigm(gi) * tanhf(gg);
                float hn = sigm(go) * tanhf(cn);
                g_c[b * Dz + d] = cn;
                g_h[b * Dz + d] = hn;
                __nv_bfloat16 hh = __float2bfloat16(hn);
                __nv_bfloat16 hl = __float2bfloat16(hn - __bfloat162float(hh));
                size_t idx = ((size_t)t * Bz + b) * Dz + d;
                g_ahi[idx] = hh;
                g_alo[idx] = hl;
            }
        }
        gbar();
    }
}

// ---------------- launcher (exactly 5 launches; 4th = loop for ncu) ----------------
extern "C" void kernel_launch(void* const* d_in, const int* in_sizes, int n_in,
                              void* d_out, int out_size) {
    const float* features = (const float*)d_in[0];
    const float* articles = (const float*)d_in[1];
    const int*   captions = (const int*)d_in[2];
    const float* emb      = (const float*)d_in[3];
    const float* att_W_w  = (const float*)d_in[4];
    const float* att_W_b  = (const float*)d_in[5];
    const float* att_U_w  = (const float*)d_in[6];
    const float* att_U_b  = (const float*)d_in[7];
    const float* att_A_w  = (const float*)d_in[8];
    const float* att_A_b  = (const float*)d_in[9];
    const float* pa_W_w   = (const float*)d_in[10];
    const float* pa_W_b   = (const float*)d_in[11];
    const float* pa_U_w   = (const float*)d_in[12];
    const float* pa_U_b   = (const float*)d_in[13];
    const float* pa_A_w   = (const float*)d_in[14];
    const float* pa_A_b   = (const float*)d_in[15];
    const float* init_h_w = (const float*)d_in[16];
    const float* init_h_b = (const float*)d_in[17];
    const float* init_c_w = (const float*)d_in[18];
    const float* init_c_b = (const float*)d_in[19];
    const float* lstm_w_ih = (const float*)d_in[20];
    const float* lstm_w_hh = (const float*)d_in[21];
    const float* lstm_b_ih = (const float*)d_in[22];
    const float* lstm_b_hh = (const float*)d_in[23];
    const float* fcn_w    = (const float*)d_in[24];
    const float* fcn_b    = (const float*)d_in[25];
    float* out = (float*)d_out;

    float *p_uf, *p_ua;
    cudaGetSymbolAddress((void**)&p_uf, g_u_feat);
    cudaGetSymbolAddress((void**)&p_ua, g_u_art);
    __nv_bfloat16 *fhi, *flo, *arhi, *arlo, *w1hi, *w1lo, *w2hi, *w2lo, *whi, *wlo, *ahi, *alo;
    cudaGetSymbolAddress((void**)&fhi, g_fhi);   cudaGetSymbolAddress((void**)&flo, g_flo);
    cudaGetSymbolAddress((void**)&arhi, g_arhi); cudaGetSymbolAddress((void**)&arlo, g_arlo);
    cudaGetSymbolAddress((void**)&w1hi, g_w1hi); cudaGetSymbolAddress((void**)&w1lo, g_w1lo);
    cudaGetSymbolAddress((void**)&w2hi, g_w2hi); cudaGetSymbolAddress((void**)&w2lo, g_w2lo);
    cudaGetSymbolAddress((void**)&whi, g_whi);   cudaGetSymbolAddress((void**)&wlo, g_wlo);
    cudaGetSymbolAddress((void**)&ahi, g_ahi);   cudaGetSymbolAddress((void**)&alo, g_alo);

    // 1: fused prologue (mean+init, embeddings, all fp32->bf16 splits)
    prologue<<<PB_TOTAL, 256>>>(features, articles, emb, captions,
                                init_h_w, init_h_b, init_c_w, init_c_b,
                                att_U_w, pa_U_w, fcn_w);
    // 2,3: u-projections on tensor cores
    gemm_mma<false><<<dim3(4, 98), 256>>>(fhi, flo, w1hi, w1lo, att_U_b, p_uf, Az, ENC);
    gemm_mma<false><<<dim3(4, 32), 256>>>(arhi, arlo, w2hi, w2lo, pa_U_b, p_ua, Az, BENC);
    // 4: persistent recurrence (ncu capture target)
    loop_kernel<<<NBLK, 256>>>(features, articles,
                               att_W_w, att_W_b, att_A_w, att_A_b,
                               pa_W_w, pa_W_b, pa_A_w, pa_A_b,
                               lstm_w_ih, lstm_w_hh, lstm_b_ih, lstm_b_hh, out);
    // 5: fcn head
    gemm_mma<true><<<dim3(236, 16), 256>>>(ahi, alo, whi, wlo, fcn_b, out, Vz, Dz);
}

// round 8
// speedup vs baseline: 1.2357x; 1.2357x over previous
#include <cuda_runtime.h>
#include <cuda_bf16.h>
#include <math.h>
#include <stdint.h>

#define Bz   64
#define Sz   32
#define NF   196
#define NP   64
#define ENC  512
#define BENC 768
#define Az   512
#define Dz   512
#define Ez   512
#define Vz   30000
#define G4   2048
#define VPAD 30208
#define NBLK 128
#define LT   512   // loop threads

#define OFF_ALPHA  61440000u
#define OFF_PA     61841408u

// ---------------- scratch ----------------
__device__ float g_u_feat[Bz * NF * Az];
__device__ float g_u_art [Bz * NP * Az];
__device__ float g_h[Bz * Dz], g_c[Bz * Dz];
__device__ float g_ctx[Bz * ENC], g_pctx[Bz * BENC];
__device__ float g_embs[Bz * Sz * Ez];
__device__ float g_gparts[4 * Bz * G4];

__device__ __nv_bfloat16 g_fhi[Bz * NF * ENC],  g_flo[Bz * NF * ENC];
__device__ __nv_bfloat16 g_arhi[Bz * NP * BENC], g_arlo[Bz * NP * BENC];
__device__ __nv_bfloat16 g_w1hi[Az * ENC],  g_w1lo[Az * ENC];
__device__ __nv_bfloat16 g_w2hi[Az * BENC], g_w2lo[Az * BENC];
__device__ __nv_bfloat16 g_whi[(size_t)VPAD * Dz], g_wlo[(size_t)VPAD * Dz];
__device__ __nv_bfloat16 g_ahi[Sz * Bz * Dz], g_alo[Sz * Bz * Dz];

__device__ unsigned g_cnt;
__device__ volatile unsigned g_gen;

__device__ __forceinline__ float wred(float v) {
#pragma unroll
    for (int o = 16; o; o >>= 1) v += __shfl_xor_sync(0xffffffffu, v, o);
    return v;
}
__device__ __forceinline__ float sigm(float x) { return 1.f / (1.f + expf(-x)); }
__device__ __forceinline__ float tanha(float x) {
    float y; asm("tanh.approx.f32 %0, %1;" : "=f"(y) : "f"(x)); return y;
}
__device__ __forceinline__ uint32_t smem_u32(const void* p) {
    uint32_t a;
    asm("{ .reg .u64 t; cvta.to.shared.u64 t, %1; cvt.u32.u64 %0, t; }" : "=r"(a) : "l"(p));
    return a;
}
__device__ __forceinline__ void mma16816(float* c, uint32_t a0, uint32_t a1, uint32_t a2,
                                         uint32_t a3, uint32_t b0, uint32_t b1) {
    asm("mma.sync.aligned.m16n8k16.row.col.f32.bf16.bf16.f32 "
        "{%0,%1,%2,%3}, {%4,%5,%6,%7}, {%8,%9}, {%0,%1,%2,%3};"
        : "+f"(c[0]), "+f"(c[1]), "+f"(c[2]), "+f"(c[3])
        : "r"(a0), "r"(a1), "r"(a2), "r"(a3), "r"(b0), "r"(b1));
}
__device__ __forceinline__ uint32_t swz(int r, int slot) {
    return (uint32_t)(r * 64 + ((slot ^ ((r >> 1) & 3)) << 4));
}
__device__ __forceinline__ void cpa16(uint32_t dst, const void* src) {
    asm volatile("cp.async.cg.shared.global [%0], [%1], 16;" :: "r"(dst), "l"(src));
}

__device__ __forceinline__ void gbar() {
    __threadfence();
    __syncthreads();
    if (threadIdx.x == 0) {
        unsigned gen = g_gen;
        if (atomicAdd(&g_cnt, 1u) == NBLK - 1) {
            g_cnt = 0;
            __threadfence();
            g_gen = gen + 1;
        } else {
            while (g_gen == gen) {}
        }
    }
    __syncthreads();
}

// ---------------- mega prologue ----------------
__device__ __forceinline__ void conv_range(const float* __restrict__ src,
                                           __nv_bfloat16* __restrict__ hi,
                                           __nv_bfloat16* __restrict__ lo,
                                           int n_src, int relblk) {
    int i = (relblk * 256 + threadIdx.x) * 4;
    float4 v = make_float4(0.f, 0.f, 0.f, 0.f);
    if (i < n_src) v = *(const float4*)(src + i);
    __nv_bfloat16 h0 = __float2bfloat16(v.x), h1 = __float2bfloat16(v.y);
    __nv_bfloat16 h2 = __float2bfloat16(v.z), h3 = __float2bfloat16(v.w);
    ((__nv_bfloat162*)(hi + i))[0] = __halves2bfloat162(h0, h1);
    ((__nv_bfloat162*)(hi + i))[1] = __halves2bfloat162(h2, h3);
    ((__nv_bfloat162*)(lo + i))[0] = __halves2bfloat162(
        __float2bfloat16(v.x - __bfloat162float(h0)), __float2bfloat16(v.y - __bfloat162float(h1)));
    ((__nv_bfloat162*)(lo + i))[1] = __halves2bfloat162(
        __float2bfloat16(v.z - __bfloat162float(h2)), __float2bfloat16(v.w - __bfloat162float(h3)));
}

#define PB_EMBED  64
#define PB_CF     2112
#define PB_CAR    8384
#define PB_CW1    11456
#define PB_CW2    11712
#define PB_CWF    12096
#define PB_TOTAL  27200

__global__ void prologue(const float* __restrict__ features, const float* __restrict__ articles,
                         const float* __restrict__ emb, const int* __restrict__ captions,
                         const float* __restrict__ ihw, const float* __restrict__ ihb,
                         const float* __restrict__ icw, const float* __restrict__ icb,
                         const float* __restrict__ attUw, const float* __restrict__ paUw,
                         const float* __restrict__ fcnw) {
    int blk = blockIdx.x, tid = threadIdx.x;
    if (blk < PB_EMBED) {
        __shared__ float x[1280];
        int b = blk, lane = tid & 31, wid = tid >> 5;
        for (int k = tid; k < ENC; k += 256) {
            float s = 0.f;
            const float* p = features + (size_t)b * NF * ENC + k;
            for (int n = 0; n < NF; n++) s += p[n * ENC];
            x[k] = s * (1.f / NF);
        }
        for (int k = tid; k < BENC; k += 256) {
            float s = 0.f;
            const float* p = articles + (size_t)b * NP * BENC + k;
            for (int n = 0; n < NP; n++) s += p[n * BENC];
            x[ENC + k] = s * (1.f / NP);
        }
        __syncthreads();
        for (int d = wid; d < Dz; d += 8) {
            float sh = 0.f, sc = 0.f;
            const float* hr = ihw + (size_t)d * 1280;
            const float* cr = icw + (size_t)d * 1280;
            for (int k = lane; k < 1280; k += 32) { float xv = x[k]; sh += hr[k] * xv; sc += cr[k] * xv; }
#pragma unroll
            for (int o = 16; o; o >>= 1) {
                sh += __shfl_xor_sync(0xffffffffu, sh, o);
                sc += __shfl_xor_sync(0xffffffffu, sc, o);
            }
            if (!lane) { g_h[b * Dz + d] = sh + ihb[d]; g_c[b * Dz + d] = sc + icb[d]; }
        }
    } else if (blk < PB_CF) {
        int bs = blk - PB_EMBED;
        int cap = captions[bs];
        const float* e = emb + (size_t)cap * Ez;
        for (int k = tid; k < Ez; k += 256) g_embs[(size_t)bs * Ez + k] = e[k];
    } else if (blk < PB_CAR) {
        conv_range(features, g_fhi, g_flo, Bz * NF * ENC, blk - PB_CF);
    } else if (blk < PB_CW1) {
        conv_range(articles, g_arhi, g_arlo, Bz * NP * BENC, blk - PB_CAR);
    } else if (blk < PB_CW2) {
        conv_range(attUw, g_w1hi, g_w1lo, Az * ENC, blk - PB_CW1);
    } else if (blk < PB_CWF) {
        conv_range(paUw, g_w2hi, g_w2lo, Az * BENC, blk - PB_CW2);
    } else {
        conv_range(fcnw, g_whi, g_wlo, Vz * Dz, blk - PB_CWF);
    }
}

// -------- split-bf16 mma.sync GEMM, cp.async double-buffered --------
template <bool PERM>
__global__ void __launch_bounds__(256)
gemm_mma(const __nv_bfloat16* __restrict__ Ahi, const __nv_bfloat16* __restrict__ Alo,
         const __nv_bfloat16* __restrict__ Whi, const __nv_bfloat16* __restrict__ Wlo,
         const float* __restrict__ bias, float* __restrict__ C, int N, int K) {
    __shared__ __align__(16) char smA[2][8192];
    __shared__ __align__(16) char smW[2][8192];
    const int tid = threadIdx.x, lane = tid & 31, wid = tid >> 5;
    const int wm = wid & 1, wn = wid >> 1;
    const int lr4 = lane >> 2, lw = lane & 3;
    const int n0 = blockIdx.x * 128, m0 = blockIdx.y * 128;
    const int kc = K >> 5, nch = 3 * kc;
    const int r1 = tid >> 2, cA = tid & 3;
    const uint32_t so1 = swz(r1, cA), so2 = swz(r1 + 64, cA);
    const uint32_t sa[2] = { smem_u32(smA[0]), smem_u32(smA[1]) };
    const uint32_t sb[2] = { smem_u32(smW[0]), smem_u32(smW[1]) };

    float acc[4][4][4] = {};

#define ISSUE(cc, st) do {                                                     \
        int part = ((cc) >= 2 * kc) ? 2 : ((cc) >= kc ? 1 : 0);                \
        int kk = ((cc) - part * kc) << 5;                                      \
        const __nv_bfloat16* As = (part == 1) ? Alo : Ahi;                     \
        const __nv_bfloat16* Ws = (part == 2) ? Wlo : Whi;                     \
        cpa16(sa[st] + so1, As + (size_t)(m0 + r1) * K + kk + cA * 8);         \
        cpa16(sa[st] + so2, As + (size_t)(m0 + r1 + 64) * K + kk + cA * 8);    \
        cpa16(sb[st] + so1, Ws + (size_t)(n0 + r1) * K + kk + cA * 8);         \
        cpa16(sb[st] + so2, Ws + (size_t)(n0 + r1 + 64) * K + kk + cA * 8);    \
        asm volatile("cp.async.commit_group;" ::: "memory");                   \
    } while (0)

    ISSUE(0, 0);
    for (int cc = 0; cc < nch; cc++) {
        const int st = cc & 1;
        if (cc + 1 < nch) {
            ISSUE(cc + 1, st ^ 1);
            asm volatile("cp.async.wait_group 1;" ::: "memory");
        } else {
            asm volatile("cp.async.wait_group 0;" ::: "memory");
        }
        __syncthreads();
        const char* pA = smA[st];
        const char* pW = smW[st];
#pragma unroll
        for (int ks = 0; ks < 2; ks++) {
            uint32_t bf[4][2];
#pragma unroll
            for (int ni = 0; ni < 4; ni++) {
                int nb = wn * 32 + ni * 8 + lr4;
                bf[ni][0] = *(const uint32_t*)(pW + swz(nb, 2 * ks) + lw * 4);
                bf[ni][1] = *(const uint32_t*)(pW + swz(nb, 2 * ks + 1) + lw * 4);
            }
#pragma unroll
            for (int mi = 0; mi < 4; mi++) {
                int ra = wm * 64 + mi * 16 + lr4, rb = ra + 8;
                uint32_t a0 = *(const uint32_t*)(pA + swz(ra, 2 * ks) + lw * 4);
                uint32_t a1 = *(const uint32_t*)(pA + swz(rb, 2 * ks) + lw * 4);
                uint32_t a2 = *(const uint32_t*)(pA + swz(ra, 2 * ks + 1) + lw * 4);
                uint32_t a3 = *(const uint32_t*)(pA + swz(rb, 2 * ks + 1) + lw * 4);
#pragma unroll
                for (int ni = 0; ni < 4; ni++)
                    mma16816(acc[mi][ni], a0, a1, a2, a3, bf[ni][0], bf[ni][1]);
            }
        }
        __syncthreads();
    }
#undef ISSUE

#pragma unroll
    for (int mi = 0; mi < 4; mi++) {
#pragma unroll
        for (int ni = 0; ni < 4; ni++) {
            int m = m0 + wm * 64 + mi * 16 + lr4;
            int n = n0 + wn * 32 + ni * 8 + lw * 2;
            if (n < N) {
                float bx = bias[n], by = bias[n + 1];
                size_t row0 = PERM ? (size_t)((m & 63) * Sz + (m >> 6)) * N : (size_t)m * N;
                size_t row1 = PERM ? (size_t)(((m + 8) & 63) * Sz + ((m + 8) >> 6)) * N
                                   : (size_t)(m + 8) * N;
                *(float2*)(C + row0 + n) = make_float2(acc[mi][ni][0] + bx, acc[mi][ni][1] + by);
                *(float2*)(C + row1 + n) = make_float2(acc[mi][ni][2] + bx, acc[mi][ni][3] + by);
            }
        }
    }
}

// ---------------- persistent loop (512 threads, 16 warps) ----------------
__device__ __forceinline__ void attend_p(float* sh, const float* __restrict__ F,
                                         const float* __restrict__ u,
                                         const float* __restrict__ Ww, const float* __restrict__ Wb,
                                         const float* __restrict__ Aw, float Ab,
                                         int b, int Nn, int Kd,
                                         float* __restrict__ ctxp, float* __restrict__ outp) {
    const int tid = threadIdx.x, lane = tid & 31, wid = tid >> 5;
    float* hsh = sh;          // 512
    float* wah = sh + 512;    // 512
    float* sc  = sh + 1024;   // 200
    float* red = sh + 1232;   // 16
    float* sm  = sh + 1248;   // 2

    hsh[tid] = g_h[b * Dz + tid];
    __syncthreads();

    // wah = h @ Ww^T + Wb  (16 warps, 32 rows each)
    for (int a = wid; a < Az; a += 16) {
        float s = 0.f;
        const float* wr_ = Ww + (size_t)a * Dz;
        for (int k = lane; k < Dz; k += 32) s += wr_[k] * hsh[k];
        s = wred(s);
        if (!lane) wah[a] = s + Wb[a];
    }
    __syncthreads();

    // scores
    for (int n = wid; n < Nn; n += 16) {
        const float* ur = u + (size_t)n * Az;
        float s = 0.f;
        for (int a = lane; a < Az; a += 32) s += tanha(ur[a] + wah[a]) * Aw[a];
        s = wred(s);
        if (!lane) sc[n] = s + Ab;
    }
    __syncthreads();

    // softmax
    float m = -1e30f;
    for (int n = tid; n < Nn; n += LT) m = fmaxf(m, sc[n]);
#pragma unroll
    for (int o = 16; o; o >>= 1) m = fmaxf(m, __shfl_xor_sync(0xffffffffu, m, o));
    if (!lane) red[wid] = m;
    __syncthreads();
    if (tid == 0) {
        float mm = red[0];
        for (int i = 1; i < 16; i++) mm = fmaxf(mm, red[i]);
        sm[0] = mm;
    }
    __syncthreads();
    float e = 0.f;
    for (int n = tid; n < Nn; n += LT) { float ex = expf(sc[n] - sm[0]); sc[n] = ex; e += ex; }
    e = wred(e);
    if (!lane) red[wid] = e;
    __syncthreads();
    if (tid == 0) {
        float ss = 0.f;
        for (int i = 0; i < 16; i++) ss += red[i];
        sm[1] = ss;
    }
    __syncthreads();
    const float inv = 1.f / sm[1];
    for (int n = tid; n < Nn; n += LT) { float al = sc[n] * inv; sc[n] = al; outp[n] = al; }
    __syncthreads();

    // ctx = alpha @ F (4-way unrolled accumulators)
    for (int k = tid; k < Kd; k += LT) {
        float a0 = 0.f, a1 = 0.f, a2 = 0.f, a3 = 0.f;
        const float* Fk = F + k;
        int n = 0;
        for (; n + 3 < Nn; n += 4) {
            a0 += sc[n] * Fk[(size_t)n * Kd];
            a1 += sc[n + 1] * Fk[(size_t)(n + 1) * Kd];
            a2 += sc[n + 2] * Fk[(size_t)(n + 2) * Kd];
            a3 += sc[n + 3] * Fk[(size_t)(n + 3) * Kd];
        }
        for (; n < Nn; n++) a0 += sc[n] * Fk[(size_t)n * Kd];
        ctxp[k] = (a0 + a1) + (a2 + a3);
    }
}

__device__ __forceinline__ void gates_p(float* sh, const float* __restrict__ w_ih,
                                        const float* __restrict__ w_hh, int s, int n0, int t) {
    float* Xs = sh;            // [16][64]
    float* Ws = sh + 1024;     // [16][32]
    const int tid = threadIdx.x;
    const int tx = tid & 7, ty = tid >> 3;      // batch ty (0..63), cols tx*4..+3
    const int xr = (tid & 255) >> 2, xc = (tid & 3) << 2;

    const float* xs;
    int Ks, kofs;
    if (s == 0)      { xs = g_embs + ((size_t)xr * Sz + t) * Ez; Ks = 512; kofs = 0; }
    else if (s == 1) { xs = g_ctx + xr * ENC;   Ks = 512; kofs = 512; }
    else if (s == 2) { xs = g_pctx + xr * BENC; Ks = 768; kofs = 1024; }
    else             { xs = g_h + xr * Dz;      Ks = 512; kofs = 0; }

    const int iters = Ks / 16;
    float acc[4] = {};
    __syncthreads();
    for (int it = 0; it < iters; it++) {
        int kl = it * 16;
        float4 xv = make_float4(0.f, 0.f, 0.f, 0.f);
        float4 wv = make_float4(0.f, 0.f, 0.f, 0.f);
        if (tid < 256) xv = *(const float4*)&xs[kl + xc];
        if (tid < 128) {
            int j = n0 + (tid >> 2);
            int kg = kl + (tid & 3) * 4;
            const float* src = (s == 3) ? &w_hh[(size_t)j * 512 + kg]
                                        : &w_ih[(size_t)j * 1792 + kofs + kg];
            wv = *(const float4*)src;
        }
        __syncthreads();
        if (tid < 256) {
            Xs[(xc + 0) * 64 + xr] = xv.x; Xs[(xc + 1) * 64 + xr] = xv.y;
            Xs[(xc + 2) * 64 + xr] = xv.z; Xs[(xc + 3) * 64 + xr] = xv.w;
        }
        if (tid < 128) {
            int n = tid >> 2, kq = (tid & 3) * 4;
            Ws[(kq + 0) * 32 + n] = wv.x; Ws[(kq + 1) * 32 + n] = wv.y;
            Ws[(kq + 2) * 32 + n] = wv.z; Ws[(kq + 3) * 32 + n] = wv.w;
        }
        __syncthreads();
#pragma unroll
        for (int k = 0; k < 16; k++) {
            float ra = Xs[k * 64 + ty];
            float rb[4];
            *(float4*)&rb[0] = *(const float4*)&Ws[k * 32 + tx * 4];
#pragma unroll
            for (int j = 0; j < 4; j++) acc[j] += ra * rb[j];
        }
        __syncthreads();
    }
#pragma unroll
    for (int j = 0; j < 4; j++)
        g_gparts[((size_t)s * Bz + ty) * G4 + n0 + tx * 4 + j] = acc[j];
}

__global__ void __launch_bounds__(LT)
loop_kernel(const float* __restrict__ features, const float* __restrict__ articles,
            const float* __restrict__ attWw, const float* __restrict__ attWb,
            const float* __restrict__ attAw, const float* __restrict__ attAb,
            const float* __restrict__ paWw, const float* __restrict__ paWb,
            const float* __restrict__ paAw, const float* __restrict__ paAb,
            const float* __restrict__ w_ih, const float* __restrict__ w_hh,
            const float* __restrict__ b_ih, const float* __restrict__ b_hh,
            float* __restrict__ out) {
    __shared__ float sh[2048];
    const int bid = blockIdx.x, tid = threadIdx.x;
    const int type = bid >> 6, b = bid & 63;

    for (int t = 0; t < Sz; t++) {
        // A: attend (wah+scores+softmax+ctx) + h/emb-dependent gate segments
        if (type == 0)
            attend_p(sh, features + (size_t)b * NF * ENC, g_u_feat + (size_t)b * NF * Az,
                     attWw, attWb, attAw, attAb[0], b, NF, ENC, g_ctx + b * ENC,
                     out + OFF_ALPHA + (size_t)(b * Sz + t) * NF);
        else
            attend_p(sh, articles + (size_t)b * NP * BENC, g_u_art + (size_t)b * NP * Az,
                     paWw, paWb, paAw, paAb[0], b, NP, BENC, g_pctx + b * BENC,
                     out + OFF_PA + (size_t)(b * Sz + t) * NP);
        __syncthreads();
        gates_p(sh, w_ih, w_hh, type ? 3 : 0, b * 32, t);
        gbar();
        // B: ctx-dependent gate segments
        gates_p(sh, w_ih, w_hh, type ? 2 : 1, b * 32, t);
        gbar();
        // C: LSTM pointwise
        if (type == 0) {
            int d = tid;
            float gi = b_ih[d] + b_hh[d];
            float gf = b_ih[512 + d] + b_hh[512 + d];
            float gg = b_ih[1024 + d] + b_hh[1024 + d];
            float go = b_ih[1536 + d] + b_hh[1536 + d];
#pragma unroll
            for (int ks = 0; ks < 4; ks++) {
                const float* gp = g_gparts + ((size_t)ks * Bz + b) * G4;
                gi += gp[d]; gf += gp[512 + d]; gg += gp[1024 + d]; go += gp[1536 + d];
            }
            float cp = g_c[b * Dz + d];
            float cn = sigm(gf) * cp + sigm(gi) * tanhf(gg);
            float hn = sigm(go) * tanhf(cn);
            g_c[b * Dz + d] = cn;
            g_h[b * Dz + d] = hn;
            __nv_bfloat16 hh = __float2bfloat16(hn);
            __nv_bfloat16 hl = __float2bfloat16(hn - __bfloat162float(hh));
            size_t idx = ((size_t)t * Bz + b) * Dz + d;
            g_ahi[idx] = hh;
            g_alo[idx] = hl;
        }
        gbar();
    }
}

// ---------------- launcher (5 launches; 4th = loop for ncu) ----------------
extern "C" void kernel_launch(void* const* d_in, const int* in_sizes, int n_in,
                              void* d_out, int out_size) {
    const float* features = (const float*)d_in[0];
    const float* articles = (const float*)d_in[1];
    const int*   captions = (const int*)d_in[2];
    const float* emb      = (const float*)d_in[3];
    const float* att_W_w  = (const float*)d_in[4];
    const float* att_W_b  = (const float*)d_in[5];
    const float* att_U_w  = (const float*)d_in[6];
    const float* att_U_b  = (const float*)d_in[7];
    const float* att_A_w  = (const float*)d_in[8];
    const float* att_A_b  = (const float*)d_in[9];
    const float* pa_W_w   = (const float*)d_in[10];
    const float* pa_W_b   = (const float*)d_in[11];
    const float* pa_U_w   = (const float*)d_in[12];
    const float* pa_U_b   = (const float*)d_in[13];
    const float* pa_A_w   = (const float*)d_in[14];
    const float* pa_A_b   = (const float*)d_in[15];
    const float* init_h_w = (const float*)d_in[16];
    const float* init_h_b = (const float*)d_in[17];
    const float* init_c_w = (const float*)d_in[18];
    const float* init_c_b = (const float*)d_in[19];
    const float* lstm_w_ih = (const float*)d_in[20];
    const float* lstm_w_hh = (const float*)d_in[21];
    const float* lstm_b_ih = (const float*)d_in[22];
    const float* lstm_b_hh = (const float*)d_in[23];
    const float* fcn_w    = (const float*)d_in[24];
    const float* fcn_b    = (const float*)d_in[25];
    float* out = (float*)d_out;

    float *p_uf, *p_ua;
    cudaGetSymbolAddress((void**)&p_uf, g_u_feat);
    cudaGetSymbolAddress((void**)&p_ua, g_u_art);
    __nv_bfloat16 *fhi, *flo, *arhi, *arlo, *w1hi, *w1lo, *w2hi, *w2lo, *whi, *wlo, *ahi, *alo;
    cudaGetSymbolAddress((void**)&fhi, g_fhi);   cudaGetSymbolAddress((void**)&flo, g_flo);
    cudaGetSymbolAddress((void**)&arhi, g_arhi); cudaGetSymbolAddress((void**)&arlo, g_arlo);
    cudaGetSymbolAddress((void**)&w1hi, g_w1hi); cudaGetSymbolAddress((void**)&w1lo, g_w1lo);
    cudaGetSymbolAddress((void**)&w2hi, g_w2hi); cudaGetSymbolAddress((void**)&w2lo, g_w2lo);
    cudaGetSymbolAddress((void**)&whi, g_whi);   cudaGetSymbolAddress((void**)&wlo, g_wlo);
    cudaGetSymbolAddress((void**)&ahi, g_ahi);   cudaGetSymbolAddress((void**)&alo, g_alo);

    prologue<<<PB_TOTAL, 256>>>(features, articles, emb, captions,
                                init_h_w, init_h_b, init_c_w, init_c_b,
                                att_U_w, pa_U_w, fcn_w);
    gemm_mma<false><<<dim3(4, 98), 256>>>(fhi, flo, w1hi, w1lo, att_U_b, p_uf, Az, ENC);
    gemm_mma<false><<<dim3(4, 32), 256>>>(arhi, arlo, w2hi, w2lo, pa_U_b, p_ua, Az, BENC);
    loop_kernel<<<NBLK, LT>>>(features, articles,
                              att_W_w, att_W_b, att_A_w, att_A_b,
                              pa_W_w, pa_W_b, pa_A_w, pa_A_b,
                              lstm_w_ih, lstm_w_hh, lstm_b_ih, lstm_b_hh, out);
    gemm_mma<true><<<dim3(236, 16), 256>>>(ahi, alo, whi, wlo, fcn_b, out, Vz, Dz);
}

// round 9
// speedup vs baseline: 1.3954x; 1.1292x over previous
#include <cuda_runtime.h>
#include <cuda_bf16.h>
#include <math.h>
#include <stdint.h>

#define Bz   64
#define Sz   32
#define NF   196
#define NP   64
#define ENC  512
#define BENC 768
#define Az   512
#define Dz   512
#define Ez   512
#define Vz   30000
#define G4   2048
#define VPAD 30208
#define NBLK 128
#define LT   512

#define OFF_ALPHA  61440000u
#define OFF_PA     61841408u

// ---------------- scratch ----------------
__device__ float g_u_feat[Bz * NF * Az];
__device__ float g_u_art [Bz * NP * Az];
__device__ float g_h[Bz * Dz], g_c[Bz * Dz];
__device__ float g_ctx[Bz * ENC], g_pctx[Bz * BENC];
__device__ float g_gparts[4 * Bz * G4];
__device__ float g_wah[2 * Bz * Az];
__device__ float g_gemb[(size_t)Bz * Sz * G4];   // precomputed emb gates, 16.8MB
__device__ float g_zbias[G4];                    // zeros

__device__ __nv_bfloat16 g_fhi[Bz * NF * ENC],  g_flo[Bz * NF * ENC];
__device__ __nv_bfloat16 g_arhi[Bz * NP * BENC], g_arlo[Bz * NP * BENC];
__device__ __nv_bfloat16 g_w1hi[Az * ENC],  g_w1lo[Az * ENC];
__device__ __nv_bfloat16 g_w2hi[Az * BENC], g_w2lo[Az * BENC];
__device__ __nv_bfloat16 g_whi[(size_t)VPAD * Dz], g_wlo[(size_t)VPAD * Dz];
__device__ __nv_bfloat16 g_ahi[Sz * Bz * Dz], g_alo[Sz * Bz * Dz];
__device__ __nv_bfloat16 g_ehi[Bz * Sz * Ez], g_elo[Bz * Sz * Ez];       // embeddings bf16
__device__ __nv_bfloat16 g_wsehi[G4 * 512], g_wselo[G4 * 512];           // w_ih[:, :512]

__device__ unsigned g_cnt;
__device__ volatile unsigned g_gen;

__device__ __forceinline__ float wred(float v) {
#pragma unroll
    for (int o = 16; o; o >>= 1) v += __shfl_xor_sync(0xffffffffu, v, o);
    return v;
}
__device__ __forceinline__ float sigm(float x) { return 1.f / (1.f + expf(-x)); }
__device__ __forceinline__ float tanha(float x) {
    float y; asm("tanh.approx.f32 %0, %1;" : "=f"(y) : "f"(x)); return y;
}
__device__ __forceinline__ uint32_t smem_u32(const void* p) {
    uint32_t a;
    asm("{ .reg .u64 t; cvta.to.shared.u64 t, %1; cvt.u32.u64 %0, t; }" : "=r"(a) : "l"(p));
    return a;
}
__device__ __forceinline__ void mma16816(float* c, uint32_t a0, uint32_t a1, uint32_t a2,
                                         uint32_t a3, uint32_t b0, uint32_t b1) {
    asm("mma.sync.aligned.m16n8k16.row.col.f32.bf16.bf16.f32 "
        "{%0,%1,%2,%3}, {%4,%5,%6,%7}, {%8,%9}, {%0,%1,%2,%3};"
        : "+f"(c[0]), "+f"(c[1]), "+f"(c[2]), "+f"(c[3])
        : "r"(a0), "r"(a1), "r"(a2), "r"(a3), "r"(b0), "r"(b1));
}
__device__ __forceinline__ uint32_t swz(int r, int slot) {
    return (uint32_t)(r * 64 + ((slot ^ ((r >> 1) & 3)) << 4));
}
__device__ __forceinline__ void cpa16(uint32_t dst, const void* src) {
    asm volatile("cp.async.cg.shared.global [%0], [%1], 16;" :: "r"(dst), "l"(src));
}

__device__ __forceinline__ void gbar() {
    __threadfence();
    __syncthreads();
    if (threadIdx.x == 0) {
        unsigned gen = g_gen;
        if (atomicAdd(&g_cnt, 1u) == NBLK - 1) {
            g_cnt = 0;
            __threadfence();
            g_gen = gen + 1;
        } else {
            while (g_gen == gen) {}
        }
    }
    __syncthreads();
}

// ---------------- prologue ----------------
__device__ __forceinline__ void conv_range(const float* __restrict__ src,
                                           __nv_bfloat16* __restrict__ hi,
                                           __nv_bfloat16* __restrict__ lo,
                                           int n_src, int relblk) {
    int i = (relblk * 256 + threadIdx.x) * 4;
    float4 v = make_float4(0.f, 0.f, 0.f, 0.f);
    if (i < n_src) v = *(const float4*)(src + i);
    __nv_bfloat16 h0 = __float2bfloat16(v.x), h1 = __float2bfloat16(v.y);
    __nv_bfloat16 h2 = __float2bfloat16(v.z), h3 = __float2bfloat16(v.w);
    ((__nv_bfloat162*)(hi + i))[0] = __halves2bfloat162(h0, h1);
    ((__nv_bfloat162*)(hi + i))[1] = __halves2bfloat162(h2, h3);
    ((__nv_bfloat162*)(lo + i))[0] = __halves2bfloat162(
        __float2bfloat16(v.x - __bfloat162float(h0)), __float2bfloat16(v.y - __bfloat162float(h1)));
    ((__nv_bfloat162*)(lo + i))[1] = __halves2bfloat162(
        __float2bfloat16(v.z - __bfloat162float(h2)), __float2bfloat16(v.w - __bfloat162float(h3)));
}

#define PB_EMBED  64
#define PB_CF     2112
#define PB_CAR    8384
#define PB_CW1    11456
#define PB_CW2    11712
#define PB_CWIH   12096
#define PB_CWF    13120
#define PB_TOTAL  28224

__global__ void prologue(const float* __restrict__ features, const float* __restrict__ articles,
                         const float* __restrict__ emb, const int* __restrict__ captions,
                         const float* __restrict__ ihw, const float* __restrict__ ihb,
                         const float* __restrict__ icw, const float* __restrict__ icb,
                         const float* __restrict__ attUw, const float* __restrict__ paUw,
                         const float* __restrict__ w_ih, const float* __restrict__ fcnw) {
    int blk = blockIdx.x, tid = threadIdx.x;
    if (blk < PB_EMBED) {
        __shared__ float x[1280];
        int b = blk, lane = tid & 31, wid = tid >> 5;
        for (int k = tid; k < ENC; k += 256) {
            float s = 0.f;
            const float* p = features + (size_t)b * NF * ENC + k;
            for (int n = 0; n < NF; n++) s += p[n * ENC];
            x[k] = s * (1.f / NF);
        }
        for (int k = tid; k < BENC; k += 256) {
            float s = 0.f;
            const float* p = articles + (size_t)b * NP * BENC + k;
            for (int n = 0; n < NP; n++) s += p[n * BENC];
            x[ENC + k] = s * (1.f / NP);
        }
        __syncthreads();
        for (int d = wid; d < Dz; d += 8) {
            float sh = 0.f, sc = 0.f;
            const float* hr = ihw + (size_t)d * 1280;
            const float* cr = icw + (size_t)d * 1280;
            for (int k = lane; k < 1280; k += 32) { float xv = x[k]; sh += hr[k] * xv; sc += cr[k] * xv; }
#pragma unroll
            for (int o = 16; o; o >>= 1) {
                sh += __shfl_xor_sync(0xffffffffu, sh, o);
                sc += __shfl_xor_sync(0xffffffffu, sc, o);
            }
            if (!lane) { g_h[b * Dz + d] = sh + ihb[d]; g_c[b * Dz + d] = sc + icb[d]; }
        }
    } else if (blk < PB_CF) {
        int bs = blk - PB_EMBED;       // b*Sz + t
        int cap = captions[bs];
        const float* e = emb + (size_t)cap * Ez;
        for (int k = tid; k < Ez; k += 256) {
            float v = e[k];
            __nv_bfloat16 h0 = __float2bfloat16(v);
            g_ehi[(size_t)bs * Ez + k] = h0;
            g_elo[(size_t)bs * Ez + k] = __float2bfloat16(v - __bfloat162float(h0));
        }
    } else if (blk < PB_CAR) {
        conv_range(features, g_fhi, g_flo, Bz * NF * ENC, blk - PB_CF);
    } else if (blk < PB_CW1) {
        conv_range(articles, g_arhi, g_arlo, Bz * NP * BENC, blk - PB_CAR);
    } else if (blk < PB_CW2) {
        conv_range(attUw, g_w1hi, g_w1lo, Az * ENC, blk - PB_CW1);
    } else if (blk < PB_CWIH) {
        conv_range(paUw, g_w2hi, g_w2lo, Az * BENC, blk - PB_CW2);
    } else if (blk < PB_CWF) {
        // packed copy of w_ih[:, :512] (strided source)
        int i = ((blk - PB_CWIH) * 256 + tid) * 4;
        int row = i >> 9, col = i & 511;
        float4 v = *(const float4*)(w_ih + (size_t)row * 1792 + col);
        __nv_bfloat16 h0 = __float2bfloat16(v.x), h1 = __float2bfloat16(v.y);
        __nv_bfloat16 h2 = __float2bfloat16(v.z), h3 = __float2bfloat16(v.w);
        ((__nv_bfloat162*)(g_wsehi + i))[0] = __halves2bfloat162(h0, h1);
        ((__nv_bfloat162*)(g_wsehi + i))[1] = __halves2bfloat162(h2, h3);
        ((__nv_bfloat162*)(g_wselo + i))[0] = __halves2bfloat162(
            __float2bfloat16(v.x - __bfloat162float(h0)), __float2bfloat16(v.y - __bfloat162float(h1)));
        ((__nv_bfloat162*)(g_wselo + i))[1] = __halves2bfloat162(
            __float2bfloat16(v.z - __bfloat162float(h2)), __float2bfloat16(v.w - __bfloat162float(h3)));
    } else {
        conv_range(fcnw, g_whi, g_wlo, Vz * Dz, blk - PB_CWF);
    }
}

// -------- split-bf16 mma.sync GEMM tile (PERM=false) --------
__device__ __forceinline__ void gemm_tile(
        const __nv_bfloat16* __restrict__ Ahi, const __nv_bfloat16* __restrict__ Alo,
        const __nv_bfloat16* __restrict__ Whi, const __nv_bfloat16* __restrict__ Wlo,
        const float* __restrict__ bias, float* __restrict__ C, int N, int K,
        int m0, int n0) {
    __shared__ __align__(16) char smA[2][8192];
    __shared__ __align__(16) char smW[2][8192];
    const int tid = threadIdx.x, lane = tid & 31, wid = tid >> 5;
    const int wm = wid & 1, wn = wid >> 1;
    const int lr4 = lane >> 2, lw = lane & 3;
    const int kc = K >> 5, nch = 3 * kc;
    const int r1 = tid >> 2, cA = tid & 3;
    const uint32_t so1 = swz(r1, cA), so2 = swz(r1 + 64, cA);
    const uint32_t sa[2] = { smem_u32(smA[0]), smem_u32(smA[1]) };
    const uint32_t sb[2] = { smem_u32(smW[0]), smem_u32(smW[1]) };
    float acc[4][4][4] = {};

#define ISSUE(cc, st) do {                                                     \
        int part = ((cc) >= 2 * kc) ? 2 : ((cc) >= kc ? 1 : 0);                \
        int kk = ((cc) - part * kc) << 5;                                      \
        const __nv_bfloat16* As = (part == 1) ? Alo : Ahi;                     \
        const __nv_bfloat16* Ws = (part == 2) ? Wlo : Whi;                     \
        cpa16(sa[st] + so1, As + (size_t)(m0 + r1) * K + kk + cA * 8);         \
        cpa16(sa[st] + so2, As + (size_t)(m0 + r1 + 64) * K + kk + cA * 8);    \
        cpa16(sb[st] + so1, Ws + (size_t)(n0 + r1) * K + kk + cA * 8);         \
        cpa16(sb[st] + so2, Ws + (size_t)(n0 + r1 + 64) * K + kk + cA * 8);    \
        asm volatile("cp.async.commit_group;" ::: "memory");                   \
    } while (0)

    ISSUE(0, 0);
    for (int cc = 0; cc < nch; cc++) {
        const int st = cc & 1;
        if (cc + 1 < nch) {
            ISSUE(cc + 1, st ^ 1);
            asm volatile("cp.async.wait_group 1;" ::: "memory");
        } else {
            asm volatile("cp.async.wait_group 0;" ::: "memory");
        }
        __syncthreads();
        const char* pA = smA[st];
        const char* pW = smW[st];
#pragma unroll
        for (int ks = 0; ks < 2; ks++) {
            uint32_t bf[4][2];
#pragma unroll
            for (int ni = 0; ni < 4; ni++) {
                int nb = wn * 32 + ni * 8 + lr4;
                bf[ni][0] = *(const uint32_t*)(pW + swz(nb, 2 * ks) + lw * 4);
                bf[ni][1] = *(const uint32_t*)(pW + swz(nb, 2 * ks + 1) + lw * 4);
            }
#pragma unroll
            for (int mi = 0; mi < 4; mi++) {
                int ra = wm * 64 + mi * 16 + lr4, rb = ra + 8;
                uint32_t a0 = *(const uint32_t*)(pA + swz(ra, 2 * ks) + lw * 4);
                uint32_t a1 = *(const uint32_t*)(pA + swz(rb, 2 * ks) + lw * 4);
                uint32_t a2 = *(const uint32_t*)(pA + swz(ra, 2 * ks + 1) + lw * 4);
                uint32_t a3 = *(const uint32_t*)(pA + swz(rb, 2 * ks + 1) + lw * 4);
#pragma unroll
                for (int ni = 0; ni < 4; ni++)
                    mma16816(acc[mi][ni], a0, a1, a2, a3, bf[ni][0], bf[ni][1]);
            }
        }
        __syncthreads();
    }
#undef ISSUE
#pragma unroll
    for (int mi = 0; mi < 4; mi++) {
#pragma unroll
        for (int ni = 0; ni < 4; ni++) {
            int m = m0 + wm * 64 + mi * 16 + lr4;
            int n = n0 + wn * 32 + ni * 8 + lw * 2;
            float bx = bias[n], by = bias[n + 1];
            *(float2*)(C + (size_t)m * N + n) = make_float2(acc[mi][ni][0] + bx, acc[mi][ni][1] + by);
            *(float2*)(C + (size_t)(m + 8) * N + n) = make_float2(acc[mi][ni][2] + bx, acc[mi][ni][3] + by);
        }
    }
}

// three GEMMs in one launch: u_feat (y<98), u_art (98<=y<130), emb-gates (y>=130)
__global__ void __launch_bounds__(256)
gemm3(const float* __restrict__ attUb, const float* __restrict__ paUb) {
    int y = blockIdx.y, x = blockIdx.x;
    if (y < 98) {
        if (x >= 4) return;
        gemm_tile(g_fhi, g_flo, g_w1hi, g_w1lo, attUb, g_u_feat, Az, ENC, y * 128, x * 128);
    } else if (y < 130) {
        if (x >= 4) return;
        gemm_tile(g_arhi, g_arlo, g_w2hi, g_w2lo, paUb, g_u_art, Az, BENC, (y - 98) * 128, x * 128);
    } else {
        gemm_tile(g_ehi, g_elo, g_wsehi, g_wselo, g_zbias, g_gemb, G4, 512, (y - 130) * 128, x * 128);
    }
}

// -------- fcn GEMM (permuted store) --------
__global__ void __launch_bounds__(256)
gemm_fcn(const float* __restrict__ bias, float* __restrict__ C) {
    const int N = Vz, K = Dz;
    __shared__ __align__(16) char smA[2][8192];
    __shared__ __align__(16) char smW[2][8192];
    const int tid = threadIdx.x, lane = tid & 31, wid = tid >> 5;
    const int wm = wid & 1, wn = wid >> 1;
    const int lr4 = lane >> 2, lw = lane & 3;
    const int n0 = blockIdx.x * 128, m0 = blockIdx.y * 128;
    const int kc = K >> 5, nch = 3 * kc;
    const int r1 = tid >> 2, cA = tid & 3;
    const uint32_t so1 = swz(r1, cA), so2 = swz(r1 + 64, cA);
    const uint32_t sa[2] = { smem_u32(smA[0]), smem_u32(smA[1]) };
    const uint32_t sb[2] = { smem_u32(smW[0]), smem_u32(smW[1]) };
    float acc[4][4][4] = {};

#define ISSUE(cc, st) do {                                                     \
        int part = ((cc) >= 2 * kc) ? 2 : ((cc) >= kc ? 1 : 0);                \
        int kk = ((cc) - part * kc) << 5;                                      \
        const __nv_bfloat16* As = (part == 1) ? g_alo : g_ahi;                 \
        const __nv_bfloat16* Ws = (part == 2) ? g_wlo : g_whi;                 \
        cpa16(sa[st] + so1, As + (size_t)(m0 + r1) * K + kk + cA * 8);         \
        cpa16(sa[st] + so2, As + (size_t)(m0 + r1 + 64) * K + kk + cA * 8);    \
        cpa16(sb[st] + so1, Ws + (size_t)(n0 + r1) * K + kk + cA * 8);         \
        cpa16(sb[st] + so2, Ws + (size_t)(n0 + r1 + 64) * K + kk + cA * 8);    \
        asm volatile("cp.async.commit_group;" ::: "memory");                   \
    } while (0)

    ISSUE(0, 0);
    for (int cc = 0; cc < nch; cc++) {
        const int st = cc & 1;
        if (cc + 1 < nch) {
            ISSUE(cc + 1, st ^ 1);
            asm volatile("cp.async.wait_group 1;" ::: "memory");
        } else {
            asm volatile("cp.async.wait_group 0;" ::: "memory");
        }
        __syncthreads();
        const char* pA = smA[st];
        const char* pW = smW[st];
#pragma unroll
        for (int ks = 0; ks < 2; ks++) {
            uint32_t bf[4][2];
#pragma unroll
            for (int ni = 0; ni < 4; ni++) {
                int nb = wn * 32 + ni * 8 + lr4;
                bf[ni][0] = *(const uint32_t*)(pW + swz(nb, 2 * ks) + lw * 4);
                bf[ni][1] = *(const uint32_t*)(pW + swz(nb, 2 * ks + 1) + lw * 4);
            }
#pragma unroll
            for (int mi = 0; mi < 4; mi++) {
                int ra = wm * 64 + mi * 16 + lr4, rb = ra + 8;
                uint32_t a0 = *(const uint32_t*)(pA + swz(ra, 2 * ks) + lw * 4);
                uint32_t a1 = *(const uint32_t*)(pA + swz(rb, 2 * ks) + lw * 4);
                uint32_t a2 = *(const uint32_t*)(pA + swz(ra, 2 * ks + 1) + lw * 4);
                uint32_t a3 = *(const uint32_t*)(pA + swz(rb, 2 * ks + 1) + lw * 4);
#pragma unroll
                for (int ni = 0; ni < 4; ni++)
                    mma16816(acc[mi][ni], a0, a1, a2, a3, bf[ni][0], bf[ni][1]);
            }
        }
        __syncthreads();
    }
#undef ISSUE
#pragma unroll
    for (int mi = 0; mi < 4; mi++) {
#pragma unroll
        for (int ni = 0; ni < 4; ni++) {
            int m = m0 + wm * 64 + mi * 16 + lr4;
            int n = n0 + wn * 32 + ni * 8 + lw * 2;
            if (n < N) {
                float bx = bias[n], by = bias[n + 1];
                size_t row0 = (size_t)((m & 63) * Sz + (m >> 6)) * N;
                size_t row1 = (size_t)(((m + 8) & 63) * Sz + ((m + 8) >> 6)) * N;
                *(float2*)(C + row0 + n) = make_float2(acc[mi][ni][0] + bx, acc[mi][ni][1] + by);
                *(float2*)(C + row1 + n) = make_float2(acc[mi][ni][2] + bx, acc[mi][ni][3] + by);
            }
        }
    }
}

// ---------------- persistent loop ----------------
__device__ __forceinline__ void attend_p(float* sh, const float* __restrict__ F,
                                         const float* __restrict__ u,
                                         const float* __restrict__ Aw, float Ab,
                                         int type, int b, int Nn, int Kd,
                                         float* __restrict__ ctxp, float* __restrict__ outp) {
    const int tid = threadIdx.x, lane = tid & 31, wid = tid >> 5;
    float* wahs = sh;          // 512
    float* aws  = sh + 512;    // 512
    float* sc   = sh + 1024;   // 200
    float* red  = sh + 1232;   // 16
    float* sm   = sh + 1248;   // 2

    wahs[tid] = g_wah[(size_t)(type * Bz + b) * Az + tid];
    aws[tid] = Aw[tid];
    __syncthreads();

    const float4* w4 = (const float4*)wahs;
    const float4* a4p = (const float4*)aws;
    for (int n = wid; n < Nn; n += 16) {
        const float4* ur4 = (const float4*)(u + (size_t)n * Az);
        float s = 0.f;
#pragma unroll
        for (int q = 0; q < 4; q++) {
            int idx = lane + q * 32;
            float4 uu = ur4[idx];
            float4 ww = w4[idx];
            float4 aa = a4p[idx];
            s += tanha(uu.x + ww.x) * aa.x + tanha(uu.y + ww.y) * aa.y +
                 tanha(uu.z + ww.z) * aa.z + tanha(uu.w + ww.w) * aa.w;
        }
        s = wred(s);
        if (!lane) sc[n] = s + Ab;
    }
    __syncthreads();

    float m = -1e30f;
    for (int n = tid; n < Nn; n += LT) m = fmaxf(m, sc[n]);
#pragma unroll
    for (int o = 16; o; o >>= 1) m = fmaxf(m, __shfl_xor_sync(0xffffffffu, m, o));
    if (!lane) red[wid] = m;
    __syncthreads();
    if (tid == 0) {
        float mm = red[0];
        for (int i = 1; i < 16; i++) mm = fmaxf(mm, red[i]);
        sm[0] = mm;
    }
    __syncthreads();
    float e = 0.f;
    for (int n = tid; n < Nn; n += LT) { float ex = expf(sc[n] - sm[0]); sc[n] = ex; e += ex; }
    e = wred(e);
    if (!lane) red[wid] = e;
    __syncthreads();
    if (tid == 0) {
        float ss = 0.f;
        for (int i = 0; i < 16; i++) ss += red[i];
        sm[1] = ss;
    }
    __syncthreads();
    const float inv = 1.f / sm[1];
    for (int n = tid; n < Nn; n += LT) { float al = sc[n] * inv; sc[n] = al; outp[n] = al; }
    __syncthreads();

    for (int k = tid; k < Kd; k += LT) {
        float a0 = 0.f, a1 = 0.f, a2 = 0.f, a3 = 0.f;
        const float* Fk = F + k;
        int n = 0;
        for (; n + 3 < Nn; n += 4) {
            a0 += sc[n] * Fk[(size_t)n * Kd];
            a1 += sc[n + 1] * Fk[(size_t)(n + 1) * Kd];
            a2 += sc[n + 2] * Fk[(size_t)(n + 2) * Kd];
            a3 += sc[n + 3] * Fk[(size_t)(n + 3) * Kd];
        }
        for (; n < Nn; n++) a0 += sc[n] * Fk[(size_t)n * Kd];
        ctxp[k] = (a0 + a1) + (a2 + a3);
    }
}

__device__ __forceinline__ void gates_p(float* sh, const float* __restrict__ w_ih,
                                        const float* __restrict__ w_hh, int s, int n0) {
    float* Xs = sh;            // [16][64]
    float* Ws = sh + 1024;     // [16][32]
    const int tid = threadIdx.x;
    const int tx = tid & 7, ty = tid >> 3;
    const int xr = (tid & 255) >> 2, xc = (tid & 3) << 2;

    const float* xs;
    int Ks, kofs;
    if (s == 1)      { xs = g_ctx + xr * ENC;   Ks = 512; kofs = 512; }
    else if (s == 2) { xs = g_pctx + xr * BENC; Ks = 768; kofs = 1024; }
    else             { xs = g_h + xr * Dz;      Ks = 512; kofs = 0; }

    const int iters = Ks / 16;
    float acc[4] = {};
    __syncthreads();
    for (int it = 0; it < iters; it++) {
        int kl = it * 16;
        float4 xv = make_float4(0.f, 0.f, 0.f, 0.f);
        float4 wv = make_float4(0.f, 0.f, 0.f, 0.f);
        if (tid < 256) xv = *(const float4*)&xs[kl + xc];
        if (tid < 128) {
            int j = n0 + (tid >> 2);
            int kg = kl + (tid & 3) * 4;
            const float* src = (s == 3) ? &w_hh[(size_t)j * 512 + kg]
                                        : &w_ih[(size_t)j * 1792 + kofs + kg];
            wv = *(const float4*)src;
        }
        __syncthreads();
        if (tid < 256) {
            Xs[(xc + 0) * 64 + xr] = xv.x; Xs[(xc + 1) * 64 + xr] = xv.y;
            Xs[(xc + 2) * 64 + xr] = xv.z; Xs[(xc + 3) * 64 + xr] = xv.w;
        }
        if (tid < 128) {
            int n = tid >> 2, kq = (tid & 3) * 4;
            Ws[(kq + 0) * 32 + n] = wv.x; Ws[(kq + 1) * 32 + n] = wv.y;
            Ws[(kq + 2) * 32 + n] = wv.z; Ws[(kq + 3) * 32 + n] = wv.w;
        }
        __syncthreads();
#pragma unroll
        for (int k = 0; k < 16; k++) {
            float ra = Xs[k * 64 + ty];
            float rb[4];
            *(float4*)&rb[0] = *(const float4*)&Ws[k * 32 + tx * 4];
#pragma unroll
            for (int j = 0; j < 4; j++) acc[j] += ra * rb[j];
        }
        __syncthreads();
    }
#pragma unroll
    for (int j = 0; j < 4; j++)
        g_gparts[((size_t)s * Bz + ty) * G4 + n0 + tx * 4 + j] = acc[j];
}

__global__ void __launch_bounds__(LT)
loop_kernel(const float* __restrict__ features, const float* __restrict__ articles,
            const float* __restrict__ attWw, const float* __restrict__ attWb,
            const float* __restrict__ attAw, const float* __restrict__ attAb,
            const float* __restrict__ paWw, const float* __restrict__ paWb,
            const float* __restrict__ paAw, const float* __restrict__ paAb,
            const float* __restrict__ w_ih, const float* __restrict__ w_hh,
            const float* __restrict__ b_ih, const float* __restrict__ b_hh,
            float* __restrict__ out) {
    __shared__ __align__(16) float sh[4352];
    const int bid = blockIdx.x, tid = threadIdx.x;
    const int lane = tid & 31, wid = tid >> 5;
    const int type = bid >> 6, b = bid & 63;
    const float* Wt = type ? paWw : attWw;
    const float* Wbv = type ? paWb : attWb;

    for (int t = 0; t < Sz; t++) {
        // ---- A: distributed wah: this block computes rows [b*8, b*8+8) for all 64 batches
        {
            const int a0 = b * 8;
            for (int i = tid; i < 1024; i += LT)
                ((float4*)sh)[i] = *(const float4*)(Wt + (size_t)(a0 + (i >> 7)) * Dz + ((i & 127) << 2));
            __syncthreads();
#pragma unroll 1
            for (int ib = 0; ib < 4; ib++) {
                int b2 = wid + ib * 16;
                const float4* hp = (const float4*)(g_h + b2 * Dz);
                float4 h4[4];
#pragma unroll
                for (int q = 0; q < 4; q++) h4[q] = hp[lane + q * 32];
#pragma unroll 1
                for (int r = 0; r < 8; r++) {
                    const float4* wr4 = (const float4*)(sh + r * 512);
                    float s = 0.f;
#pragma unroll
                    for (int q = 0; q < 4; q++) {
                        float4 wv = wr4[lane + q * 32];
                        s += wv.x * h4[q].x + wv.y * h4[q].y + wv.z * h4[q].z + wv.w * h4[q].w;
                    }
                    s = wred(s);
                    if (!lane) g_wah[(size_t)(type * Bz + b2) * Az + a0 + r] = s + Wbv[a0 + r];
                }
            }
        }
        gbar();
        // ---- B: attend + (type1) s3 gates
        if (type == 0)
            attend_p(sh, features + (size_t)b * NF * ENC, g_u_feat + (size_t)b * NF * Az,
                     attAw, attAb[0], 0, b, NF, ENC, g_ctx + b * ENC,
                     out + OFF_ALPHA + (size_t)(b * Sz + t) * NF);
        else
            attend_p(sh, articles + (size_t)b * NP * BENC, g_u_art + (size_t)b * NP * Az,
                     paAw, paAb[0], 1, b, NP, BENC, g_pctx + b * BENC,
                     out + OFF_PA + (size_t)(b * Sz + t) * NP);
        if (type == 1) gates_p(sh, w_ih, w_hh, 3, b * 32);
        gbar();
        // ---- C: ctx-dependent gates
        gates_p(sh, w_ih, w_hh, type ? 2 : 1, b * 32);
        gbar();
        // ---- D: LSTM pointwise
        if (type == 0) {
            int d = tid;
            const float* ge = g_gemb + (size_t)(b * Sz + t) * G4;
            float gi = b_ih[d] + b_hh[d] + ge[d];
            float gf = b_ih[512 + d] + b_hh[512 + d] + ge[512 + d];
            float gg = b_ih[1024 + d] + b_hh[1024 + d] + ge[1024 + d];
            float go = b_ih[1536 + d] + b_hh[1536 + d] + ge[1536 + d];
#pragma unroll
            for (int ks = 1; ks < 4; ks++) {
                const float* gp = g_gparts + ((size_t)ks * Bz + b) * G4;
                gi += gp[d]; gf += gp[512 + d]; gg += gp[1024 + d]; go += gp[1536 + d];
            }
            float cp = g_c[b * Dz + d];
            float cn = sigm(gf) * cp + sigm(gi) * tanhf(gg);
            float hn = sigm(go) * tanhf(cn);
            g_c[b * Dz + d] = cn;
            g_h[b * Dz + d] = hn;
            __nv_bfloat16 hh = __float2bfloat16(hn);
            __nv_bfloat16 hl = __float2bfloat16(hn - __bfloat162float(hh));
            size_t idx = ((size_t)t * Bz + b) * Dz + d;
            g_ahi[idx] = hh;
            g_alo[idx] = hl;
        }
        gbar();
    }
}

// ---------------- launcher: 4 launches; #4 = fcn (ncu target) ----------------
extern "C" void kernel_launch(void* const* d_in, const int* in_sizes, int n_in,
                              void* d_out, int out_size) {
    const float* features = (const float*)d_in[0];
    const float* articles = (const float*)d_in[1];
    const int*   captions = (const int*)d_in[2];
    const float* emb      = (const float*)d_in[3];
    const float* att_W_w  = (const float*)d_in[4];
    const float* att_W_b  = (const float*)d_in[5];
    const float* att_U_w  = (const float*)d_in[6];
    const float* att_U_b  = (const float*)d_in[7];
    const float* att_A_w  = (const float*)d_in[8];
    const float* att_A_b  = (const float*)d_in[9];
    const float* pa_W_w   = (const float*)d_in[10];
    const float* pa_W_b   = (const float*)d_in[11];
    const float* pa_U_w   = (const float*)d_in[12];
    const float* pa_U_b   = (const float*)d_in[13];
    const float* pa_A_w   = (const float*)d_in[14];
    const float* pa_A_b   = (const float*)d_in[15];
    const float* init_h_w = (const float*)d_in[16];
    const float* init_h_b = (const float*)d_in[17];
    const float* init_c_w = (const float*)d_in[18];
    const float* init_c_b = (const float*)d_in[19];
    const float* lstm_w_ih = (const float*)d_in[20];
    const float* lstm_w_hh = (const float*)d_in[21];
    const float* lstm_b_ih = (const float*)d_in[22];
    const float* lstm_b_hh = (const float*)d_in[23];
    const float* fcn_w    = (const float*)d_in[24];
    const float* fcn_b    = (const float*)d_in[25];
    float* out = (float*)d_out;

    prologue<<<PB_TOTAL, 256>>>(features, articles, emb, captions,
                                init_h_w, init_h_b, init_c_w, init_c_b,
                                att_U_w, pa_U_w, lstm_w_ih, fcn_w);
    gemm3<<<dim3(16, 146), 256>>>(att_U_b, pa_U_b);
    loop_kernel<<<NBLK, LT>>>(features, articles,
                              att_W_w, att_W_b, att_A_w, att_A_b,
                              pa_W_w, pa_W_b, pa_A_w, pa_A_b,
                              lstm_w_ih, lstm_w_hh, lstm_b_ih, lstm_b_hh, out);
    gemm_fcn<<<dim3(236, 16), 256>>>(fcn_b, out);
}

// round 10
// speedup vs baseline: 1.9154x; 1.3726x over previous
#include <cuda_runtime.h>
#include <cuda_bf16.h>
#include <math.h>
#include <stdint.h>

#define Bz   64
#define Sz   32
#define NF   196
#define NP   64
#define ENC  512
#define BENC 768
#define Az   512
#define Dz   512
#define Ez   512
#define Vz   30000
#define G4   2048
#define VPAD 30208
#define NBLK 128
#define LT   512

#define OFF_ALPHA  61440000u
#define OFF_PA     61841408u

// ---------------- scratch ----------------
__device__ float g_u_feat[Bz * NF * Az];
__device__ float g_u_art [Bz * NP * Az];
__device__ float g_h[Bz * Dz], g_c[Bz * Dz];
__device__ float g_ctx[Bz * ENC], g_pctx[Bz * BENC];
__device__ float g_gparts[4 * Bz * G4];
__device__ float g_wah[2 * Bz * Az];
__device__ float g_gemb[(size_t)Bz * Sz * G4];
__device__ float g_zbias[G4];

__device__ __nv_bfloat16 g_fhi[Bz * NF * ENC],  g_flo[Bz * NF * ENC];
__device__ __nv_bfloat16 g_arhi[Bz * NP * BENC], g_arlo[Bz * NP * BENC];
__device__ __nv_bfloat16 g_w1hi[Az * ENC],  g_w1lo[Az * ENC];
__device__ __nv_bfloat16 g_w2hi[Az * BENC], g_w2lo[Az * BENC];
__device__ __nv_bfloat16 g_whi[(size_t)VPAD * Dz], g_wlo[(size_t)VPAD * Dz];
__device__ __nv_bfloat16 g_ahi[Sz * Bz * Dz], g_alo[Sz * Bz * Dz];
__device__ __nv_bfloat16 g_ehi[Bz * Sz * Ez], g_elo[Bz * Sz * Ez];
__device__ __nv_bfloat16 g_wsehi[G4 * 512], g_wselo[G4 * 512];

__device__ unsigned g_cnt;
__device__ volatile unsigned g_gen;

__device__ __forceinline__ float wred(float v) {
#pragma unroll
    for (int o = 16; o; o >>= 1) v += __shfl_xor_sync(0xffffffffu, v, o);
    return v;
}
__device__ __forceinline__ float sigm(float x) { return 1.f / (1.f + expf(-x)); }
__device__ __forceinline__ float tanha(float x) {
    float y; asm("tanh.approx.f32 %0, %1;" : "=f"(y) : "f"(x)); return y;
}
__device__ __forceinline__ uint32_t smem_u32(const void* p) {
    uint32_t a;
    asm("{ .reg .u64 t; cvta.to.shared.u64 t, %1; cvt.u32.u64 %0, t; }" : "=r"(a) : "l"(p));
    return a;
}
__device__ __forceinline__ void mma16816(float* c, uint32_t a0, uint32_t a1, uint32_t a2,
                                         uint32_t a3, uint32_t b0, uint32_t b1) {
    asm("mma.sync.aligned.m16n8k16.row.col.f32.bf16.bf16.f32 "
        "{%0,%1,%2,%3}, {%4,%5,%6,%7}, {%8,%9}, {%0,%1,%2,%3};"
        : "+f"(c[0]), "+f"(c[1]), "+f"(c[2]), "+f"(c[3])
        : "r"(a0), "r"(a1), "r"(a2), "r"(a3), "r"(b0), "r"(b1));
}
__device__ __forceinline__ void ldsm4(uint32_t& r0, uint32_t& r1, uint32_t& r2, uint32_t& r3,
                                      uint32_t addr) {
    asm volatile("ldmatrix.sync.aligned.m8n8.x4.shared.b16 {%0,%1,%2,%3}, [%4];"
                 : "=r"(r0), "=r"(r1), "=r"(r2), "=r"(r3) : "r"(addr));
}
__device__ __forceinline__ uint32_t swz(int r, int slot) {
    return (uint32_t)(r * 64 + ((slot ^ ((r >> 1) & 3)) << 4));
}
__device__ __forceinline__ void cpa16(uint32_t dst, const void* src) {
    asm volatile("cp.async.cg.shared.global [%0], [%1], 16;" :: "r"(dst), "l"(src));
}

__device__ __forceinline__ void gbar() {
    __threadfence();
    __syncthreads();
    if (threadIdx.x == 0) {
        unsigned gen = g_gen;
        if (atomicAdd(&g_cnt, 1u) == NBLK - 1) {
            g_cnt = 0;
            __threadfence();
            g_gen = gen + 1;
        } else {
            while (g_gen == gen) {}
        }
    }
    __syncthreads();
}

// ---------------- prologue ----------------
__device__ __forceinline__ void conv_range(const float* __restrict__ src,
                                           __nv_bfloat16* __restrict__ hi,
                                           __nv_bfloat16* __restrict__ lo,
                                           int n_src, int relblk) {
    int i = (relblk * 256 + threadIdx.x) * 4;
    float4 v = make_float4(0.f, 0.f, 0.f, 0.f);
    if (i < n_src) v = *(const float4*)(src + i);
    __nv_bfloat16 h0 = __float2bfloat16(v.x), h1 = __float2bfloat16(v.y);
    __nv_bfloat16 h2 = __float2bfloat16(v.z), h3 = __float2bfloat16(v.w);
    ((__nv_bfloat162*)(hi + i))[0] = __halves2bfloat162(h0, h1);
    ((__nv_bfloat162*)(hi + i))[1] = __halves2bfloat162(h2, h3);
    ((__nv_bfloat162*)(lo + i))[0] = __halves2bfloat162(
        __float2bfloat16(v.x - __bfloat162float(h0)), __float2bfloat16(v.y - __bfloat162float(h1)));
    ((__nv_bfloat162*)(lo + i))[1] = __halves2bfloat162(
        __float2bfloat16(v.z - __bfloat162float(h2)), __float2bfloat16(v.w - __bfloat162float(h3)));
}

#define PB_EMBED  64
#define PB_CF     2112
#define PB_CAR    8384
#define PB_CW1    11456
#define PB_CW2    11712
#define PB_CWIH   12096
#define PB_CWF    13120
#define PB_TOTAL  28224

__global__ void prologue(const float* __restrict__ features, const float* __restrict__ articles,
                         const float* __restrict__ emb, const int* __restrict__ captions,
                         const float* __restrict__ ihw, const float* __restrict__ ihb,
                         const float* __restrict__ icw, const float* __restrict__ icb,
                         const float* __restrict__ attUw, const float* __restrict__ paUw,
                         const float* __restrict__ w_ih, const float* __restrict__ fcnw) {
    int blk = blockIdx.x, tid = threadIdx.x;
    if (blk < PB_EMBED) {
        __shared__ float x[1280];
        int b = blk, lane = tid & 31, wid = tid >> 5;
        for (int k = tid; k < ENC; k += 256) {
            float s = 0.f;
            const float* p = features + (size_t)b * NF * ENC + k;
            for (int n = 0; n < NF; n++) s += p[n * ENC];
            x[k] = s * (1.f / NF);
        }
        for (int k = tid; k < BENC; k += 256) {
            float s = 0.f;
            const float* p = articles + (size_t)b * NP * BENC + k;
            for (int n = 0; n < NP; n++) s += p[n * BENC];
            x[ENC + k] = s * (1.f / NP);
        }
        __syncthreads();
        for (int d = wid; d < Dz; d += 8) {
            float sh = 0.f, sc = 0.f;
            const float* hr = ihw + (size_t)d * 1280;
            const float* cr = icw + (size_t)d * 1280;
            for (int k = lane; k < 1280; k += 32) { float xv = x[k]; sh += hr[k] * xv; sc += cr[k] * xv; }
#pragma unroll
            for (int o = 16; o; o >>= 1) {
                sh += __shfl_xor_sync(0xffffffffu, sh, o);
                sc += __shfl_xor_sync(0xffffffffu, sc, o);
            }
            if (!lane) { g_h[b * Dz + d] = sh + ihb[d]; g_c[b * Dz + d] = sc + icb[d]; }
        }
    } else if (blk < PB_CF) {
        int bs = blk - PB_EMBED;
        int cap = captions[bs];
        const float* e = emb + (size_t)cap * Ez;
        for (int k = tid; k < Ez; k += 256) {
            float v = e[k];
            __nv_bfloat16 h0 = __float2bfloat16(v);
            g_ehi[(size_t)bs * Ez + k] = h0;
            g_elo[(size_t)bs * Ez + k] = __float2bfloat16(v - __bfloat162float(h0));
        }
    } else if (blk < PB_CAR) {
        conv_range(features, g_fhi, g_flo, Bz * NF * ENC, blk - PB_CF);
    } else if (blk < PB_CW1) {
        conv_range(articles, g_arhi, g_arlo, Bz * NP * BENC, blk - PB_CAR);
    } else if (blk < PB_CW2) {
        conv_range(attUw, g_w1hi, g_w1lo, Az * ENC, blk - PB_CW1);
    } else if (blk < PB_CWIH) {
        conv_range(paUw, g_w2hi, g_w2lo, Az * BENC, blk - PB_CW2);
    } else if (blk < PB_CWF) {
        int i = ((blk - PB_CWIH) * 256 + tid) * 4;
        int row = i >> 9, col = i & 511;
        float4 v = *(const float4*)(w_ih + (size_t)row * 1792 + col);
        __nv_bfloat16 h0 = __float2bfloat16(v.x), h1 = __float2bfloat16(v.y);
        __nv_bfloat16 h2 = __float2bfloat16(v.z), h3 = __float2bfloat16(v.w);
        ((__nv_bfloat162*)(g_wsehi + i))[0] = __halves2bfloat162(h0, h1);
        ((__nv_bfloat162*)(g_wsehi + i))[1] = __halves2bfloat162(h2, h3);
        ((__nv_bfloat162*)(g_wselo + i))[0] = __halves2bfloat162(
            __float2bfloat16(v.x - __bfloat162float(h0)), __float2bfloat16(v.y - __bfloat162float(h1)));
        ((__nv_bfloat162*)(g_wselo + i))[1] = __halves2bfloat162(
            __float2bfloat16(v.z - __bfloat162float(h2)), __float2bfloat16(v.w - __bfloat162float(h3)));
    } else {
        conv_range(fcnw, g_whi, g_wlo, Vz * Dz, blk - PB_CWF);
    }
}

// -------- split-bf16 mma.sync GEMM tile (ldmatrix operand feed) --------
__device__ __forceinline__ void gemm_tile(
        const __nv_bfloat16* __restrict__ Ahi, const __nv_bfloat16* __restrict__ Alo,
        const __nv_bfloat16* __restrict__ Whi, const __nv_bfloat16* __restrict__ Wlo,
        const float* __restrict__ bias, float* __restrict__ C, int N, int K,
        int m0, int n0, bool perm) {
    __shared__ __align__(16) char smA[2][8192];
    __shared__ __align__(16) char smW[2][8192];
    const int tid = threadIdx.x, lane = tid & 31, wid = tid >> 5;
    const int wm = wid & 1, wn = wid >> 1;
    const int lr4 = lane >> 2, lw = lane & 3;
    const int t8 = lane >> 3, rw = lane & 7;
    const int kc = K >> 5, nch = 3 * kc;
    const int r1 = tid >> 2, cA = tid & 3;
    const uint32_t so1 = swz(r1, cA), so2 = swz(r1 + 64, cA);
    const uint32_t sa[2] = { smem_u32(smA[0]), smem_u32(smA[1]) };
    const uint32_t sb[2] = { smem_u32(smW[0]), smem_u32(smW[1]) };
    float acc[4][4][4] = {};

#define ISSUE(cc, st) do {                                                     \
        int part = ((cc) >= 2 * kc) ? 2 : ((cc) >= kc ? 1 : 0);                \
        int kk = ((cc) - part * kc) << 5;                                      \
        const __nv_bfloat16* As = (part == 1) ? Alo : Ahi;                     \
        const __nv_bfloat16* Ws = (part == 2) ? Wlo : Whi;                     \
        cpa16(sa[st] + so1, As + (size_t)(m0 + r1) * K + kk + cA * 8);         \
        cpa16(sa[st] + so2, As + (size_t)(m0 + r1 + 64) * K + kk + cA * 8);    \
        cpa16(sb[st] + so1, Ws + (size_t)(n0 + r1) * K + kk + cA * 8);         \
        cpa16(sb[st] + so2, Ws + (size_t)(n0 + r1 + 64) * K + kk + cA * 8);    \
        asm volatile("cp.async.commit_group;" ::: "memory");                   \
    } while (0)

    ISSUE(0, 0);
    for (int cc = 0; cc < nch; cc++) {
        const int st = cc & 1;
        if (cc + 1 < nch) {
            ISSUE(cc + 1, st ^ 1);
            asm volatile("cp.async.wait_group 1;" ::: "memory");
        } else {
            asm volatile("cp.async.wait_group 0;" ::: "memory");
        }
        __syncthreads();
        const uint32_t saSt = sa[st], sbSt = sb[st];
#pragma unroll
        for (int ks = 0; ks < 2; ks++) {
            uint32_t bf[4][2];
#pragma unroll
            for (int nip = 0; nip < 2; nip++) {
                uint32_t r0, r1b, r2, r3;
                ldsm4(r0, r1b, r2, r3,
                      sbSt + swz(wn * 32 + nip * 16 + ((t8 >> 1) << 3) + rw, 2 * ks + (t8 & 1)));
                bf[nip * 2][0] = r0; bf[nip * 2][1] = r1b;
                bf[nip * 2 + 1][0] = r2; bf[nip * 2 + 1][1] = r3;
            }
#pragma unroll
            for (int mi = 0; mi < 4; mi++) {
                uint32_t a0, a1, a2, a3;
                ldsm4(a0, a1, a2, a3,
                      saSt + swz(wm * 64 + mi * 16 + ((t8 & 1) << 3) + rw, 2 * ks + (t8 >> 1)));
#pragma unroll
                for (int ni = 0; ni < 4; ni++)
                    mma16816(acc[mi][ni], a0, a1, a2, a3, bf[ni][0], bf[ni][1]);
            }
        }
        __syncthreads();
    }
#undef ISSUE
#pragma unroll
    for (int mi = 0; mi < 4; mi++) {
#pragma unroll
        for (int ni = 0; ni < 4; ni++) {
            int m = m0 + wm * 64 + mi * 16 + lr4;
            int n = n0 + wn * 32 + ni * 8 + lw * 2;
            if (n < N) {
                float bx = bias[n], by = bias[n + 1];
                size_t row0 = perm ? (size_t)((m & 63) * Sz + (m >> 6)) * N : (size_t)m * N;
                size_t row1 = perm ? (size_t)(((m + 8) & 63) * Sz + ((m + 8) >> 6)) * N
                                   : (size_t)(m + 8) * N;
                *(float2*)(C + row0 + n) = make_float2(acc[mi][ni][0] + bx, acc[mi][ni][1] + by);
                *(float2*)(C + row1 + n) = make_float2(acc[mi][ni][2] + bx, acc[mi][ni][3] + by);
            }
        }
    }
}

__global__ void __launch_bounds__(256)
gemm3(const float* __restrict__ attUb, const float* __restrict__ paUb) {
    int y = blockIdx.y, x = blockIdx.x;
    if (y < 98) {
        if (x >= 4) return;
        gemm_tile(g_fhi, g_flo, g_w1hi, g_w1lo, attUb, g_u_feat, Az, ENC, y * 128, x * 128, false);
    } else if (y < 130) {
        if (x >= 4) return;
        gemm_tile(g_arhi, g_arlo, g_w2hi, g_w2lo, paUb, g_u_art, Az, BENC, (y - 98) * 128, x * 128, false);
    } else {
        gemm_tile(g_ehi, g_elo, g_wsehi, g_wselo, g_zbias, g_gemb, G4, 512, (y - 130) * 128, x * 128, false);
    }
}

__global__ void __launch_bounds__(256)
gemm_fcn(const float* __restrict__ bias, float* __restrict__ C) {
    gemm_tile(g_ahi, g_alo, g_whi, g_wlo, bias, C, Vz, Dz,
              blockIdx.y * 128, blockIdx.x * 128, true);
}

// ---------------- persistent loop ----------------
__device__ __forceinline__ void attend_p(float* sh, const float* __restrict__ F,
                                         const float* __restrict__ u,
                                         const float* __restrict__ Aw, float Ab,
                                         int type, int b, int Nn, int Kd,
                                         float* __restrict__ ctxp, float* __restrict__ outp) {
    const int tid = threadIdx.x, lane = tid & 31, wid = tid >> 5;
    float* wahs = sh;
    float* aws  = sh + 512;
    float* sc   = sh + 1024;
    float* red  = sh + 1232;
    float* sm   = sh + 1248;

    wahs[tid] = g_wah[(size_t)(type * Bz + b) * Az + tid];
    aws[tid] = Aw[tid];
    __syncthreads();

    const float4* w4 = (const float4*)wahs;
    const float4* a4p = (const float4*)aws;
    for (int n = wid; n < Nn; n += 16) {
        const float4* ur4 = (const float4*)(u + (size_t)n * Az);
        float s = 0.f;
#pragma unroll
        for (int q = 0; q < 4; q++) {
            int idx = lane + q * 32;
            float4 uu = ur4[idx];
            float4 ww = w4[idx];
            float4 aa = a4p[idx];
            s += tanha(uu.x + ww.x) * aa.x + tanha(uu.y + ww.y) * aa.y +
                 tanha(uu.z + ww.z) * aa.z + tanha(uu.w + ww.w) * aa.w;
        }
        s = wred(s);
        if (!lane) sc[n] = s + Ab;
    }
    __syncthreads();

    float m = -1e30f;
    for (int n = tid; n < Nn; n += LT) m = fmaxf(m, sc[n]);
#pragma unroll
    for (int o = 16; o; o >>= 1) m = fmaxf(m, __shfl_xor_sync(0xffffffffu, m, o));
    if (!lane) red[wid] = m;
    __syncthreads();
    if (tid == 0) {
        float mm = red[0];
        for (int i = 1; i < 16; i++) mm = fmaxf(mm, red[i]);
        sm[0] = mm;
    }
    __syncthreads();
    float e = 0.f;
    for (int n = tid; n < Nn; n += LT) { float ex = expf(sc[n] - sm[0]); sc[n] = ex; e += ex; }
    e = wred(e);
    if (!lane) red[wid] = e;
    __syncthreads();
    if (tid == 0) {
        float ss = 0.f;
        for (int i = 0; i < 16; i++) ss += red[i];
        sm[1] = ss;
    }
    __syncthreads();
    const float inv = 1.f / sm[1];
    for (int n = tid; n < Nn; n += LT) { float al = sc[n] * inv; sc[n] = al; outp[n] = al; }
    __syncthreads();

    // ctx: 8-way unrolled accumulator chains
    for (int k = tid; k < Kd; k += LT) {
        float a0 = 0.f, a1 = 0.f, a2 = 0.f, a3 = 0.f, a4 = 0.f, a5 = 0.f, a6 = 0.f, a7 = 0.f;
        const float* Fk = F + k;
        int n = 0;
        for (; n + 7 < Nn; n += 8) {
            a0 += sc[n] * Fk[(size_t)n * Kd];
            a1 += sc[n + 1] * Fk[(size_t)(n + 1) * Kd];
            a2 += sc[n + 2] * Fk[(size_t)(n + 2) * Kd];
            a3 += sc[n + 3] * Fk[(size_t)(n + 3) * Kd];
            a4 += sc[n + 4] * Fk[(size_t)(n + 4) * Kd];
            a5 += sc[n + 5] * Fk[(size_t)(n + 5) * Kd];
            a6 += sc[n + 6] * Fk[(size_t)(n + 6) * Kd];
            a7 += sc[n + 7] * Fk[(size_t)(n + 7) * Kd];
        }
        for (; n < Nn; n++) a0 += sc[n] * Fk[(size_t)n * Kd];
        ctxp[k] = ((a0 + a1) + (a2 + a3)) + ((a4 + a5) + (a6 + a7));
    }
}

// gates: 3-stage cp.async pipeline; smem X[3][64][20], W[3][32][20] (padded rows)
__device__ __forceinline__ void gates_p(float* sh, const float* __restrict__ w_ih,
                                        const float* __restrict__ w_hh, int s, int n0) {
    float* Xb = sh;                 // 3 * 1280 floats
    float* Wb = sh + 3840;          // 3 * 640 floats
    const int tid = threadIdx.x;
    const int tx = tid & 7, ty = tid >> 3;     // ty = batch 0..63
    const float* xbase;
    int Ks, kofs, xstride;
    if (s == 1)      { xbase = g_ctx;  Ks = 512; kofs = 512;  xstride = ENC; }
    else if (s == 2) { xbase = g_pctx; Ks = 768; kofs = 1024; xstride = BENC; }
    else             { xbase = g_h;    Ks = 512; kofs = 0;    xstride = Dz; }
    const int iters = Ks / 16;
    const uint32_t shx = smem_u32(Xb), shw = smem_u32(Wb);
    const int xr = tid >> 2, xq = tid & 3;     // X loaders: tid<256
    const int wn_ = tid >> 2, wq = tid & 3;    // W loaders: tid<128
    float acc[4] = {};
    __syncthreads();   // previous phase's smem reads complete before cp.async writes

#define GISS(it) do { int _st = (it) % 3; int _kl = (it) * 16;                                 \
        if (tid < 256) cpa16(shx + (uint32_t)(_st * 1280 + xr * 20 + xq * 4) * 4,              \
                             xbase + (size_t)xr * xstride + _kl + xq * 4);                     \
        if (tid < 128) {                                                                       \
            const float* _src = (s == 3) ? (w_hh + (size_t)(n0 + wn_) * 512 + _kl + wq * 4)    \
                                         : (w_ih + (size_t)(n0 + wn_) * 1792 + kofs + _kl + wq * 4); \
            cpa16(shw + (uint32_t)(_st * 640 + wn_ * 20 + wq * 4) * 4, _src);                  \
        }                                                                                      \
        asm volatile("cp.async.commit_group;" ::: "memory");                                   \
    } while (0)

    GISS(0); GISS(1);
    for (int it = 0; it < iters; it++) {
        asm volatile("cp.async.wait_group 1;" ::: "memory");
        __syncthreads();
        if (it + 2 < iters) GISS(it + 2);
        const int st = it % 3;
        const float4* xv = (const float4*)(Xb + st * 1280 + ty * 20);
        float4 x0 = xv[0], x1 = xv[1], x2 = xv[2], x3 = xv[3];
        const float* wrow = Wb + st * 640;
#pragma unroll
        for (int j = 0; j < 4; j++) {
            const float4* w4 = (const float4*)(wrow + (tx + 8 * j) * 20);
            float4 w0 = w4[0], w1 = w4[1], w2 = w4[2], w3 = w4[3];
            acc[j] += x0.x * w0.x + x0.y * w0.y + x0.z * w0.z + x0.w * w0.w
                    + x1.x * w1.x + x1.y * w1.y + x1.z * w1.z + x1.w * w1.w
                    + x2.x * w2.x + x2.y * w2.y + x2.z * w2.z + x2.w * w2.w
                    + x3.x * w3.x + x3.y * w3.y + x3.z * w3.z + x3.w * w3.w;
        }
    }
#undef GISS
#pragma unroll
    for (int j = 0; j < 4; j++)
        g_gparts[((size_t)s * Bz + ty) * G4 + n0 + tx + 8 * j] = acc[j];
}

__global__ void __launch_bounds__(LT)
loop_kernel(const float* __restrict__ features, const float* __restrict__ articles,
            const float* __restrict__ attWw, const float* __restrict__ attWb,
            const float* __restrict__ attAw, const float* __restrict__ attAb,
            const float* __restrict__ paWw, const float* __restrict__ paWb,
            const float* __restrict__ paAw, const float* __restrict__ paAb,
            const float* __restrict__ w_ih, const float* __restrict__ w_hh,
            const float* __restrict__ b_ih, const float* __restrict__ b_hh,
            float* __restrict__ out) {
    __shared__ __align__(16) float sh[5888];
    const int bid = blockIdx.x, tid = threadIdx.x;
    const int lane = tid & 31, wid = tid >> 5;
    const int type = bid >> 6, b = bid & 63;
    const float* Wt = type ? paWw : attWw;
    const float* Wbv = type ? paWb : attWb;

    for (int t = 0; t < Sz; t++) {
        // ---- A: distributed wah (this block: rows [b*8, b*8+8) for all 64 batches)
        {
            const int a0 = b * 8;
            for (int i = tid; i < 1024; i += LT)
                ((float4*)sh)[i] = *(const float4*)(Wt + (size_t)(a0 + (i >> 7)) * Dz + ((i & 127) << 2));
            __syncthreads();
#pragma unroll 1
            for (int ib = 0; ib < 4; ib++) {
                int b2 = wid + ib * 16;
                const float4* hp = (const float4*)(g_h + b2 * Dz);
                float4 h4[4];
#pragma unroll
                for (int q = 0; q < 4; q++) h4[q] = hp[lane + q * 32];
#pragma unroll 1
                for (int r = 0; r < 8; r++) {
                    const float4* wr4 = (const float4*)(sh + r * 512);
                    float s = 0.f;
#pragma unroll
                    for (int q = 0; q < 4; q++) {
                        float4 wv = wr4[lane + q * 32];
                        s += wv.x * h4[q].x + wv.y * h4[q].y + wv.z * h4[q].z + wv.w * h4[q].w;
                    }
                    s = wred(s);
                    if (!lane) g_wah[(size_t)(type * Bz + b2) * Az + a0 + r] = s + Wbv[a0 + r];
                }
            }
        }
        gbar();
        // ---- B: attend + (type1) s3 gates
        if (type == 0)
            attend_p(sh, features + (size_t)b * NF * ENC, g_u_feat + (size_t)b * NF * Az,
                     attAw, attAb[0], 0, b, NF, ENC, g_ctx + b * ENC,
                     out + OFF_ALPHA + (size_t)(b * Sz + t) * NF);
        else
            attend_p(sh, articles + (size_t)b * NP * BENC, g_u_art + (size_t)b * NP * Az,
                     paAw, paAb[0], 1, b, NP, BENC, g_pctx + b * BENC,
                     out + OFF_PA + (size_t)(b * Sz + t) * NP);
        if (type == 1) gates_p(sh, w_ih, w_hh, 3, b * 32);
        gbar();
        // ---- C: ctx-dependent gates
        gates_p(sh, w_ih, w_hh, type ? 2 : 1, b * 32);
        gbar();
        // ---- D: LSTM pointwise
        if (type == 0) {
            int d = tid;
            const float* ge = g_gemb + (size_t)(b * Sz + t) * G4;
            float gi = b_ih[d] + b_hh[d] + ge[d];
            float gf = b_ih[512 + d] + b_hh[512 + d] + ge[512 + d];
            float gg = b_ih[1024 + d] + b_hh[1024 + d] + ge[1024 + d];
            float go = b_ih[1536 + d] + b_hh[1536 + d] + ge[1536 + d];
#pragma unroll
            for (int ks = 1; ks < 4; ks++) {
                const float* gp = g_gparts + ((size_t)ks * Bz + b) * G4;
                gi += gp[d]; gf += gp[512 + d]; gg += gp[1024 + d]; go += gp[1536 + d];
            }
            float cp = g_c[b * Dz + d];
            float cn = sigm(gf) * cp + sigm(gi) * tanhf(gg);
            float hn = sigm(go) * tanhf(cn);
            g_c[b * Dz + d] = cn;
            g_h[b * Dz + d] = hn;
            __nv_bfloat16 hh = __float2bfloat16(hn);
            __nv_bfloat16 hl = __float2bfloat16(hn - __bfloat162float(hh));
            size_t idx = ((size_t)t * Bz + b) * Dz + d;
            g_ahi[idx] = hh;
            g_alo[idx] = hl;
        }
        gbar();
    }
}

// ---------------- launcher: 4 launches; #4 = gemm_fcn (ncu target) ----------------
extern "C" void kernel_launch(void* const* d_in, const int* in_sizes, int n_in,
                              void* d_out, int out_size) {
    const float* features = (const float*)d_in[0];
    const float* articles = (const float*)d_in[1];
    const int*   captions = (const int*)d_in[2];
    const float* emb      = (const float*)d_in[3];
    const float* att_W_w  = (const float*)d_in[4];
    const float* att_W_b  = (const float*)d_in[5];
    const float* att_U_w  = (const float*)d_in[6];
    const float* att_U_b  = (const float*)d_in[7];
    const float* att_A_w  = (const float*)d_in[8];
    const float* att_A_b  = (const float*)d_in[9];
    const float* pa_W_w   = (const float*)d_in[10];
    const float* pa_W_b   = (const float*)d_in[11];
    const float* pa_U_w   = (const float*)d_in[12];
    const float* pa_U_b   = (const float*)d_in[13];
    const float* pa_A_w   = (const float*)d_in[14];
    const float* pa_A_b   = (const float*)d_in[15];
    const float* init_h_w = (const float*)d_in[16];
    const float* init_h_b = (const float*)d_in[17];
    const float* init_c_w = (const float*)d_in[18];
    const float* init_c_b = (const float*)d_in[19];
    const float* lstm_w_ih = (const float*)d_in[20];
    const float* lstm_w_hh = (const float*)d_in[21];
    const float* lstm_b_ih = (const float*)d_in[22];
    const float* lstm_b_hh = (const float*)d_in[23];
    const float* fcn_w    = (const float*)d_in[24];
    const float* fcn_b    = (const float*)d_in[25];
    float* out = (float*)d_out;

    prologue<<<PB_TOTAL, 256>>>(features, articles, emb, captions,
                                init_h_w, init_h_b, init_c_w, init_c_b,
                                att_U_w, pa_U_w, lstm_w_ih, fcn_w);
    gemm3<<<dim3(16, 146), 256>>>(att_U_b, pa_U_b);
    loop_kernel<<<NBLK, LT>>>(features, articles,
                              att_W_w, att_W_b, att_A_w, att_A_b,
                              pa_W_w, pa_W_b, pa_A_w, pa_A_b,
                              lstm_w_ih, lstm_w_hh, lstm_b_ih, lstm_b_hh, out);
    gemm_fcn<<<dim3(236, 16), 256>>>(fcn_b, out);
}

// round 11
// speedup vs baseline: 2.8404x; 1.4830x over previous
#include <cuda_runtime.h>
#include <cuda_bf16.h>
#include <math.h>
#include <stdint.h>

#define Bz   64
#define Sz   32
#define NF   196
#define NP   64
#define ENC  512
#define BENC 768
#define Az   512
#define Dz   512
#define Ez   512
#define Vz   30000
#define G4   2048
#define KP   1792        // packed gates K: ctx 512 | pctx 768 | h 512
#define VPAD 30208
#define NBLK 128
#define LT   512

#define OFF_ALPHA  61440000u
#define OFF_PA     61841408u

// ---------------- scratch ----------------
__device__ float g_u_feat[Bz * NF * Az];
__device__ float g_u_art [Bz * NP * Az];
__device__ float g_h[Bz * Dz], g_c[Bz * Dz];
__device__ float g_gparts8[8 * Bz * G4];         // per-ksplit partial gates
__device__ float g_wah[2 * Bz * Az];
__device__ float g_gemb[(size_t)Bz * Sz * G4];
__device__ float g_zbias[G4];

__device__ __nv_bfloat16 g_fhi[Bz * NF * ENC],  g_flo[Bz * NF * ENC];
__device__ __nv_bfloat16 g_arhi[Bz * NP * BENC], g_arlo[Bz * NP * BENC];
__device__ __nv_bfloat16 g_w1hi[Az * ENC],  g_w1lo[Az * ENC];
__device__ __nv_bfloat16 g_w2hi[Az * BENC], g_w2lo[Az * BENC];
__device__ __nv_bfloat16 g_whi[(size_t)VPAD * Dz], g_wlo[(size_t)VPAD * Dz];
__device__ __nv_bfloat16 g_ahi[Sz * Bz * Dz], g_alo[Sz * Bz * Dz];
__device__ __nv_bfloat16 g_ehi[Bz * Sz * Ez], g_elo[Bz * Sz * Ez];
__device__ __nv_bfloat16 g_wsehi[G4 * 512], g_wselo[G4 * 512];
__device__ __nv_bfloat16 g_wghi[(size_t)G4 * KP], g_wglo[(size_t)G4 * KP];   // packed gates W
__device__ __nv_bfloat16 g_xhi[Bz * KP], g_xlo[Bz * KP];                      // [ctx|pctx|h] splits

__device__ unsigned g_cnt;
__device__ volatile unsigned g_gen;

__device__ __forceinline__ float wred(float v) {
#pragma unroll
    for (int o = 16; o; o >>= 1) v += __shfl_xor_sync(0xffffffffu, v, o);
    return v;
}
__device__ __forceinline__ float sigm(float x) { return 1.f / (1.f + expf(-x)); }
__device__ __forceinline__ float tanha(float x) {
    float y; asm("tanh.approx.f32 %0, %1;" : "=f"(y) : "f"(x)); return y;
}
__device__ __forceinline__ uint32_t smem_u32(const void* p) {
    uint32_t a;
    asm("{ .reg .u64 t; cvta.to.shared.u64 t, %1; cvt.u32.u64 %0, t; }" : "=r"(a) : "l"(p));
    return a;
}
__device__ __forceinline__ void mma16816(float* c, uint32_t a0, uint32_t a1, uint32_t a2,
                                         uint32_t a3, uint32_t b0, uint32_t b1) {
    asm("mma.sync.aligned.m16n8k16.row.col.f32.bf16.bf16.f32 "
        "{%0,%1,%2,%3}, {%4,%5,%6,%7}, {%8,%9}, {%0,%1,%2,%3};"
        : "+f"(c[0]), "+f"(c[1]), "+f"(c[2]), "+f"(c[3])
        : "r"(a0), "r"(a1), "r"(a2), "r"(a3), "r"(b0), "r"(b1));
}
__device__ __forceinline__ void ldsm4(uint32_t& r0, uint32_t& r1, uint32_t& r2, uint32_t& r3,
                                      uint32_t addr) {
    asm volatile("ldmatrix.sync.aligned.m8n8.x4.shared.b16 {%0,%1,%2,%3}, [%4];"
                 : "=r"(r0), "=r"(r1), "=r"(r2), "=r"(r3) : "r"(addr));
}
__device__ __forceinline__ uint32_t swz(int r, int slot) {
    return (uint32_t)(r * 64 + ((slot ^ ((r >> 1) & 3)) << 4));
}
__device__ __forceinline__ void cpa16(uint32_t dst, const void* src) {
    asm volatile("cp.async.cg.shared.global [%0], [%1], 16;" :: "r"(dst), "l"(src));
}
__device__ __forceinline__ void split_store(__nv_bfloat16* hi, __nv_bfloat16* lo,
                                            size_t idx, float v) {
    __nv_bfloat16 h = __float2bfloat16(v);
    hi[idx] = h;
    lo[idx] = __float2bfloat16(v - __bfloat162float(h));
}

__device__ __forceinline__ void gbar() {
    __threadfence();
    __syncthreads();
    if (threadIdx.x == 0) {
        unsigned gen = g_gen;
        if (atomicAdd(&g_cnt, 1u) == NBLK - 1) {
            g_cnt = 0;
            __threadfence();
            g_gen = gen + 1;
        } else {
            while (g_gen == gen) {}
        }
    }
    __syncthreads();
}

// ---------------- prologue ----------------
__device__ __forceinline__ void conv_range(const float* __restrict__ src,
                                           __nv_bfloat16* __restrict__ hi,
                                           __nv_bfloat16* __restrict__ lo,
                                           int n_src, int relblk) {
    int i = (relblk * 256 + threadIdx.x) * 4;
    float4 v = make_float4(0.f, 0.f, 0.f, 0.f);
    if (i < n_src) v = *(const float4*)(src + i);
    __nv_bfloat16 h0 = __float2bfloat16(v.x), h1 = __float2bfloat16(v.y);
    __nv_bfloat16 h2 = __float2bfloat16(v.z), h3 = __float2bfloat16(v.w);
    ((__nv_bfloat162*)(hi + i))[0] = __halves2bfloat162(h0, h1);
    ((__nv_bfloat162*)(hi + i))[1] = __halves2bfloat162(h2, h3);
    ((__nv_bfloat162*)(lo + i))[0] = __halves2bfloat162(
        __float2bfloat16(v.x - __bfloat162float(h0)), __float2bfloat16(v.y - __bfloat162float(h1)));
    ((__nv_bfloat162*)(lo + i))[1] = __halves2bfloat162(
        __float2bfloat16(v.z - __bfloat162float(h2)), __float2bfloat16(v.w - __bfloat162float(h3)));
}

#define PB_EMBED  64
#define PB_CF     2112
#define PB_CAR    8384
#define PB_CW1    11456
#define PB_CW2    11712
#define PB_CWIH   12096
#define PB_CWG    13120
#define PB_CWF    16704
#define PB_TOTAL  31704

__global__ void prologue(const float* __restrict__ features, const float* __restrict__ articles,
                         const float* __restrict__ emb, const int* __restrict__ captions,
                         const float* __restrict__ ihw, const float* __restrict__ ihb,
                         const float* __restrict__ icw, const float* __restrict__ icb,
                         const float* __restrict__ attUw, const float* __restrict__ paUw,
                         const float* __restrict__ w_ih, const float* __restrict__ w_hh,
                         const float* __restrict__ fcnw) {
    int blk = blockIdx.x, tid = threadIdx.x;
    if (blk < PB_EMBED) {
        __shared__ float x[1280];
        int b = blk, lane = tid & 31, wid = tid >> 5;
        for (int k = tid; k < ENC; k += 256) {
            float s = 0.f;
            const float* p = features + (size_t)b * NF * ENC + k;
            for (int n = 0; n < NF; n++) s += p[n * ENC];
            x[k] = s * (1.f / NF);
        }
        for (int k = tid; k < BENC; k += 256) {
            float s = 0.f;
            const float* p = articles + (size_t)b * NP * BENC + k;
            for (int n = 0; n < NP; n++) s += p[n * BENC];
            x[ENC + k] = s * (1.f / NP);
        }
        __syncthreads();
        for (int d = wid; d < Dz; d += 8) {
            float sh = 0.f, sc = 0.f;
            const float* hr = ihw + (size_t)d * 1280;
            const float* cr = icw + (size_t)d * 1280;
            for (int k = lane; k < 1280; k += 32) { float xv = x[k]; sh += hr[k] * xv; sc += cr[k] * xv; }
#pragma unroll
            for (int o = 16; o; o >>= 1) {
                sh += __shfl_xor_sync(0xffffffffu, sh, o);
                sc += __shfl_xor_sync(0xffffffffu, sc, o);
            }
            if (!lane) {
                float h0 = sh + ihb[d];
                g_h[b * Dz + d] = h0;
                g_c[b * Dz + d] = sc + icb[d];
                split_store(g_xhi, g_xlo, (size_t)b * KP + 1280 + d, h0);
            }
        }
    } else if (blk < PB_CF) {
        int bs = blk - PB_EMBED;
        int cap = captions[bs];
        const float* e = emb + (size_t)cap * Ez;
        for (int k = tid; k < Ez; k += 256)
            split_store(g_ehi, g_elo, (size_t)bs * Ez + k, e[k]);
    } else if (blk < PB_CAR) {
        conv_range(features, g_fhi, g_flo, Bz * NF * ENC, blk - PB_CF);
    } else if (blk < PB_CW1) {
        conv_range(articles, g_arhi, g_arlo, Bz * NP * BENC, blk - PB_CAR);
    } else if (blk < PB_CW2) {
        conv_range(attUw, g_w1hi, g_w1lo, Az * ENC, blk - PB_CW1);
    } else if (blk < PB_CWIH) {
        conv_range(paUw, g_w2hi, g_w2lo, Az * BENC, blk - PB_CW2);
    } else if (blk < PB_CWG) {
        // packed w_ih[:, :512] (emb part for precomputed gemb GEMM)
        int i = ((blk - PB_CWIH) * 256 + tid) * 4;
        int row = i >> 9, col = i & 511;
        float4 v = *(const float4*)(w_ih + (size_t)row * 1792 + col);
        __nv_bfloat16 h0 = __float2bfloat16(v.x), h1 = __float2bfloat16(v.y);
        __nv_bfloat16 h2 = __float2bfloat16(v.z), h3 = __float2bfloat16(v.w);
        ((__nv_bfloat162*)(g_wsehi + i))[0] = __halves2bfloat162(h0, h1);
        ((__nv_bfloat162*)(g_wsehi + i))[1] = __halves2bfloat162(h2, h3);
        ((__nv_bfloat162*)(g_wselo + i))[0] = __halves2bfloat162(
            __float2bfloat16(v.x - __bfloat162float(h0)), __float2bfloat16(v.y - __bfloat162float(h1)));
        ((__nv_bfloat162*)(g_wselo + i))[1] = __halves2bfloat162(
            __float2bfloat16(v.z - __bfloat162float(h2)), __float2bfloat16(v.w - __bfloat162float(h3)));
    } else if (blk < PB_CWF) {
        // packed gates W: [ctx | pctx | h] = w_ih[:,512:1792] | w_hh
        int i = ((blk - PB_CWG) * 256 + tid) * 4;
        int j = i / KP, col = i % KP;
        const float* src = (col < 1280) ? (w_ih + (size_t)j * 1792 + 512 + col)
                                        : (w_hh + (size_t)j * 512 + (col - 1280));
        float4 v = *(const float4*)src;
        __nv_bfloat16 h0 = __float2bfloat16(v.x), h1 = __float2bfloat16(v.y);
        __nv_bfloat16 h2 = __float2bfloat16(v.z), h3 = __float2bfloat16(v.w);
        ((__nv_bfloat162*)(g_wghi + i))[0] = __halves2bfloat162(h0, h1);
        ((__nv_bfloat162*)(g_wghi + i))[1] = __halves2bfloat162(h2, h3);
        ((__nv_bfloat162*)(g_wglo + i))[0] = __halves2bfloat162(
            __float2bfloat16(v.x - __bfloat162float(h0)), __float2bfloat16(v.y - __bfloat162float(h1)));
        ((__nv_bfloat162*)(g_wglo + i))[1] = __halves2bfloat162(
            __float2bfloat16(v.z - __bfloat162float(h2)), __float2bfloat16(v.w - __bfloat162float(h3)));
    } else {
        conv_range(fcnw, g_whi, g_wlo, Vz * Dz, blk - PB_CWF);
    }
}

// -------- split-bf16 mma.sync GEMM tile (ldmatrix feed) --------
__device__ __forceinline__ void gemm_tile(
        const __nv_bfloat16* __restrict__ Ahi, const __nv_bfloat16* __restrict__ Alo,
        const __nv_bfloat16* __restrict__ Whi, const __nv_bfloat16* __restrict__ Wlo,
        const float* __restrict__ bias, float* __restrict__ C, int N, int K,
        int m0, int n0, bool perm) {
    __shared__ __align__(16) char smA[2][8192];
    __shared__ __align__(16) char smW[2][8192];
    const int tid = threadIdx.x, lane = tid & 31, wid = tid >> 5;
    const int wm = wid & 1, wn = wid >> 1;
    const int lr4 = lane >> 2, lw = lane & 3;
    const int t8 = lane >> 3, rw = lane & 7;
    const int kc = K >> 5, nch = 3 * kc;
    const int r1 = tid >> 2, cA = tid & 3;
    const uint32_t so1 = swz(r1, cA), so2 = swz(r1 + 64, cA);
    const uint32_t sa[2] = { smem_u32(smA[0]), smem_u32(smA[1]) };
    const uint32_t sb[2] = { smem_u32(smW[0]), smem_u32(smW[1]) };
    float acc[4][4][4] = {};

#define ISSUE(cc, st) do {                                                     \
        int part = ((cc) >= 2 * kc) ? 2 : ((cc) >= kc ? 1 : 0);                \
        int kk = ((cc) - part * kc) << 5;                                      \
        const __nv_bfloat16* As = (part == 1) ? Alo : Ahi;                     \
        const __nv_bfloat16* Ws = (part == 2) ? Wlo : Whi;                     \
        cpa16(sa[st] + so1, As + (size_t)(m0 + r1) * K + kk + cA * 8);         \
        cpa16(sa[st] + so2, As + (size_t)(m0 + r1 + 64) * K + kk + cA * 8);    \
        cpa16(sb[st] + so1, Ws + (size_t)(n0 + r1) * K + kk + cA * 8);         \
        cpa16(sb[st] + so2, Ws + (size_t)(n0 + r1 + 64) * K + kk + cA * 8);    \
        asm volatile("cp.async.commit_group;" ::: "memory");                   \
    } while (0)

    ISSUE(0, 0);
    for (int cc = 0; cc < nch; cc++) {
        const int st = cc & 1;
        if (cc + 1 < nch) {
            ISSUE(cc + 1, st ^ 1);
            asm volatile("cp.async.wait_group 1;" ::: "memory");
        } else {
            asm volatile("cp.async.wait_group 0;" ::: "memory");
        }
        __syncthreads();
        const uint32_t saSt = sa[st], sbSt = sb[st];
#pragma unroll
        for (int ks = 0; ks < 2; ks++) {
            uint32_t bf[4][2];
#pragma unroll
            for (int nip = 0; nip < 2; nip++) {
                uint32_t r0, r1b, r2, r3;
                ldsm4(r0, r1b, r2, r3,
                      sbSt + swz(wn * 32 + nip * 16 + ((t8 >> 1) << 3) + rw, 2 * ks + (t8 & 1)));
                bf[nip * 2][0] = r0; bf[nip * 2][1] = r1b;
                bf[nip * 2 + 1][0] = r2; bf[nip * 2 + 1][1] = r3;
            }
#pragma unroll
            for (int mi = 0; mi < 4; mi++) {
                uint32_t a0, a1, a2, a3;
                ldsm4(a0, a1, a2, a3,
                      saSt + swz(wm * 64 + mi * 16 + ((t8 & 1) << 3) + rw, 2 * ks + (t8 >> 1)));
#pragma unroll
                for (int ni = 0; ni < 4; ni++)
                    mma16816(acc[mi][ni], a0, a1, a2, a3, bf[ni][0], bf[ni][1]);
            }
        }
        __syncthreads();
    }
#undef ISSUE
#pragma unroll
    for (int mi = 0; mi < 4; mi++) {
#pragma unroll
        for (int ni = 0; ni < 4; ni++) {
            int m = m0 + wm * 64 + mi * 16 + lr4;
            int n = n0 + wn * 32 + ni * 8 + lw * 2;
            if (n < N) {
                float bx = bias[n], by = bias[n + 1];
                size_t row0 = perm ? (size_t)((m & 63) * Sz + (m >> 6)) * N : (size_t)m * N;
                size_t row1 = perm ? (size_t)(((m + 8) & 63) * Sz + ((m + 8) >> 6)) * N
                                   : (size_t)(m + 8) * N;
                *(float2*)(C + row0 + n) = make_float2(acc[mi][ni][0] + bx, acc[mi][ni][1] + by);
                *(float2*)(C + row1 + n) = make_float2(acc[mi][ni][2] + bx, acc[mi][ni][3] + by);
            }
        }
    }
}

__global__ void __launch_bounds__(256)
gemm3(const float* __restrict__ attUb, const float* __restrict__ paUb) {
    int y = blockIdx.y, x = blockIdx.x;
    if (y < 98) {
        if (x >= 4) return;
        gemm_tile(g_fhi, g_flo, g_w1hi, g_w1lo, attUb, g_u_feat, Az, ENC, y * 128, x * 128, false);
    } else if (y < 130) {
        if (x >= 4) return;
        gemm_tile(g_arhi, g_arlo, g_w2hi, g_w2lo, paUb, g_u_art, Az, BENC, (y - 98) * 128, x * 128, false);
    } else {
        gemm_tile(g_ehi, g_elo, g_wsehi, g_wselo, g_zbias, g_gemb, G4, 512, (y - 130) * 128, x * 128, false);
    }
}

__global__ void __launch_bounds__(256)
gemm_fcn(const float* __restrict__ bias, float* __restrict__ C) {
    gemm_tile(g_ahi, g_alo, g_whi, g_wlo, bias, C, Vz, Dz,
              blockIdx.y * 128, blockIdx.x * 128, true);
}

// ---------------- persistent loop ----------------
__device__ __forceinline__ void attend_p(float* sh, const float* __restrict__ F,
                                         const float* __restrict__ u,
                                         const float* __restrict__ Aw, float Ab,
                                         int type, int b, int Nn, int Kd, int xoff,
                                         float* __restrict__ outp) {
    const int tid = threadIdx.x, lane = tid & 31, wid = tid >> 5;
    float* wahs = sh;
    float* aws  = sh + 512;
    float* sc   = sh + 1024;
    float* red  = sh + 1232;
    float* sm   = sh + 1248;

    wahs[tid] = g_wah[(size_t)(type * Bz + b) * Az + tid];
    aws[tid] = Aw[tid];
    __syncthreads();

    const float4* w4 = (const float4*)wahs;
    const float4* a4p = (const float4*)aws;
    for (int n = wid; n < Nn; n += 16) {
        const float4* ur4 = (const float4*)(u + (size_t)n * Az);
        float s = 0.f;
#pragma unroll
        for (int q = 0; q < 4; q++) {
            int idx = lane + q * 32;
            float4 uu = ur4[idx];
            float4 ww = w4[idx];
            float4 aa = a4p[idx];
            s += tanha(uu.x + ww.x) * aa.x + tanha(uu.y + ww.y) * aa.y +
                 tanha(uu.z + ww.z) * aa.z + tanha(uu.w + ww.w) * aa.w;
        }
        s = wred(s);
        if (!lane) sc[n] = s + Ab;
    }
    __syncthreads();

    float m = -1e30f;
    for (int n = tid; n < Nn; n += LT) m = fmaxf(m, sc[n]);
#pragma unroll
    for (int o = 16; o; o >>= 1) m = fmaxf(m, __shfl_xor_sync(0xffffffffu, m, o));
    if (!lane) red[wid] = m;
    __syncthreads();
    if (tid == 0) {
        float mm = red[0];
        for (int i = 1; i < 16; i++) mm = fmaxf(mm, red[i]);
        sm[0] = mm;
    }
    __syncthreads();
    float e = 0.f;
    for (int n = tid; n < Nn; n += LT) { float ex = expf(sc[n] - sm[0]); sc[n] = ex; e += ex; }
    e = wred(e);
    if (!lane) red[wid] = e;
    __syncthreads();
    if (tid == 0) {
        float ss = 0.f;
        for (int i = 0; i < 16; i++) ss += red[i];
        sm[1] = ss;
    }
    __syncthreads();
    const float inv = 1.f / sm[1];
    for (int n = tid; n < Nn; n += LT) { float al = sc[n] * inv; sc[n] = al; outp[n] = al; }
    __syncthreads();

    // ctx: thread owns 4 k's (float4 loads); write split-bf16 into X
    int k4 = tid * 4;
    if (k4 < Kd) {
        float a0 = 0.f, a1 = 0.f, a2 = 0.f, a3 = 0.f;
        const float* Fk = F + k4;
        for (int n = 0; n < Nn; n++) {
            float4 f = *(const float4*)(Fk + (size_t)n * Kd);
            float al = sc[n];
            a0 += al * f.x; a1 += al * f.y; a2 += al * f.z; a3 += al * f.w;
        }
        size_t base = (size_t)b * KP + xoff + k4;
        __nv_bfloat16 h0 = __float2bfloat16(a0), h1 = __float2bfloat16(a1);
        __nv_bfloat16 h2 = __float2bfloat16(a2), h3 = __float2bfloat16(a3);
        ((__nv_bfloat162*)(g_xhi + base))[0] = __halves2bfloat162(h0, h1);
        ((__nv_bfloat162*)(g_xhi + base))[1] = __halves2bfloat162(h2, h3);
        ((__nv_bfloat162*)(g_xlo + base))[0] = __halves2bfloat162(
            __float2bfloat16(a0 - __bfloat162float(h0)), __float2bfloat16(a1 - __bfloat162float(h1)));
        ((__nv_bfloat162*)(g_xlo + base))[1] = __halves2bfloat162(
            __float2bfloat16(a2 - __bfloat162float(h2)), __float2bfloat16(a3 - __bfloat162float(h3)));
    }
}

// tensor-core gates: block = (nt, ks): 64 x 128 tile over K-split of 224 (x3 parts)
__device__ __forceinline__ void gates_mma(float* sh, int nt, int ks) {
    const int tid = threadIdx.x, lane = tid & 31, wid = tid >> 5;
    const int wn = wid & 7, mh = wid >> 3;
    const int lr4 = lane >> 2, lw = lane & 3;
    const int t8 = lane >> 3, rw = lane & 7;
    const int koff = ks * 224;
    // smem: X[2][64x64B] at 0 / 4KB ; W[2][128x64B] at 8KB / 16KB
    char* smem = (char*)sh;
    const uint32_t sx[2] = { smem_u32(smem), smem_u32(smem + 4096) };
    const uint32_t sw[2] = { smem_u32(smem + 8192), smem_u32(smem + 16384) };
    const int xr = tid >> 2, xq = tid & 3;   // X: tid<256 (r 0-63); W: all (r 0-127)
    float acc[2][2][4] = {};

#define GISS(cc, st) do {                                                          \
        int part = (cc) / 7;                                                       \
        int kk = koff + ((cc) % 7) * 32;                                           \
        const __nv_bfloat16* Xs_ = (part == 1) ? g_xlo : g_xhi;                    \
        const __nv_bfloat16* Ws_ = (part == 2) ? g_wglo : g_wghi;                  \
        if (tid < 256) cpa16(sx[st] + swz(xr, xq), Xs_ + (size_t)xr * KP + kk + xq * 8); \
        cpa16(sw[st] + swz(xr & 127, xq), Ws_ + (size_t)(nt * 128 + (xr & 127)) * KP + kk + xq * 8); \
        asm volatile("cp.async.commit_group;" ::: "memory");                       \
    } while (0)

    GISS(0, 0);
    for (int cc = 0; cc < 21; cc++) {
        const int st = cc & 1;
        if (cc + 1 < 21) {
            GISS(cc + 1, st ^ 1);
            asm volatile("cp.async.wait_group 1;" ::: "memory");
        } else {
            asm volatile("cp.async.wait_group 0;" ::: "memory");
        }
        __syncthreads();
        const uint32_t sxSt = sx[st], swSt = sw[st];
#pragma unroll
        for (int ks2 = 0; ks2 < 2; ks2++) {
            uint32_t b0, b1, b2, b3;
            ldsm4(b0, b1, b2, b3,
                  swSt + swz(wn * 16 + ((t8 >> 1) << 3) + rw, 2 * ks2 + (t8 & 1)));
#pragma unroll
            for (int mi = 0; mi < 2; mi++) {
                uint32_t a0, a1, a2, a3;
                ldsm4(a0, a1, a2, a3,
                      sxSt + swz(mh * 32 + mi * 16 + ((t8 & 1) << 3) + rw, 2 * ks2 + (t8 >> 1)));
                mma16816(acc[mi][0], a0, a1, a2, a3, b0, b1);
                mma16816(acc[mi][1], a0, a1, a2, a3, b2, b3);
            }
        }
        __syncthreads();
    }
#undef GISS
#pragma unroll
    for (int mi = 0; mi < 2; mi++) {
#pragma unroll
        for (int ni = 0; ni < 2; ni++) {
            int m = mh * 32 + mi * 16 + lr4;
            int n = nt * 128 + wn * 16 + ni * 8 + lw * 2;
            *(float2*)(g_gparts8 + ((size_t)ks * Bz + m) * G4 + n) =
                make_float2(acc[mi][ni][0], acc[mi][ni][1]);
            *(float2*)(g_gparts8 + ((size_t)ks * Bz + m + 8) * G4 + n) =
                make_float2(acc[mi][ni][2], acc[mi][ni][3]);
        }
    }
}

__global__ void __launch_bounds__(LT)
loop_kernel(const float* __restrict__ features, const float* __restrict__ articles,
            const float* __restrict__ attWw, const float* __restrict__ attWb,
            const float* __restrict__ attAw, const float* __restrict__ attAb,
            const float* __restrict__ paWw, const float* __restrict__ paWb,
            const float* __restrict__ paAw, const float* __restrict__ paAb,
            const float* __restrict__ b_ih, const float* __restrict__ b_hh,
            float* __restrict__ out) {
    __shared__ __align__(16) float sh[6144];   // 24KB
    const int bid = blockIdx.x, tid = threadIdx.x;
    const int lane = tid & 31, wid = tid >> 5;
    const int type = bid >> 6, b = bid & 63;
    const float* Wt = type ? paWw : attWw;
    const float* Wbv = type ? paWb : attWb;

    for (int t = 0; t < Sz; t++) {
        // ---- A: distributed wah (rows [b*8, b*8+8) for all 64 batches)
        {
            const int a0 = b * 8;
            for (int i = tid; i < 1024; i += LT)
                ((float4*)sh)[i] = *(const float4*)(Wt + (size_t)(a0 + (i >> 7)) * Dz + ((i & 127) << 2));
            __syncthreads();
#pragma unroll 1
            for (int ib = 0; ib < 4; ib++) {
                int b2 = wid + ib * 16;
                const float4* hp = (const float4*)(g_h + b2 * Dz);
                float4 h4[4];
#pragma unroll
                for (int q = 0; q < 4; q++) h4[q] = hp[lane + q * 32];
#pragma unroll 1
                for (int r = 0; r < 8; r++) {
                    const float4* wr4 = (const float4*)(sh + r * 512);
                    float s = 0.f;
#pragma unroll
                    for (int q = 0; q < 4; q++) {
                        float4 wv = wr4[lane + q * 32];
                        s += wv.x * h4[q].x + wv.y * h4[q].y + wv.z * h4[q].z + wv.w * h4[q].w;
                    }
                    s = wred(s);
                    if (!lane) g_wah[(size_t)(type * Bz + b2) * Az + a0 + r] = s + Wbv[a0 + r];
                }
            }
        }
        gbar();
        // ---- B: attention; ctx/pctx written as split-bf16 into X
        if (type == 0)
            attend_p(sh, features + (size_t)b * NF * ENC, g_u_feat + (size_t)b * NF * Az,
                     attAw, attAb[0], 0, b, NF, ENC, 0,
                     out + OFF_ALPHA + (size_t)(b * Sz + t) * NF);
        else
            attend_p(sh, articles + (size_t)b * NP * BENC, g_u_art + (size_t)b * NP * Az,
                     paAw, paAb[0], 1, b, NP, BENC, 512,
                     out + OFF_PA + (size_t)(b * Sz + t) * NP);
        gbar();
        // ---- C: tensor-core gates (all 128 blocks; 16 n-tiles x 8 k-splits)
        gates_mma(sh, bid & 15, bid >> 4);
        gbar();
        // ---- D: LSTM pointwise (type0 blocks)
        if (type == 0) {
            int d = tid;
            const float* ge = g_gemb + (size_t)(b * Sz + t) * G4;
            float gi = b_ih[d] + b_hh[d] + ge[d];
            float gf = b_ih[512 + d] + b_hh[512 + d] + ge[512 + d];
            float gg = b_ih[1024 + d] + b_hh[1024 + d] + ge[1024 + d];
            float go = b_ih[1536 + d] + b_hh[1536 + d] + ge[1536 + d];
#pragma unroll
            for (int ks = 0; ks < 8; ks++) {
                const float* gp = g_gparts8 + ((size_t)ks * Bz + b) * G4;
                gi += gp[d]; gf += gp[512 + d]; gg += gp[1024 + d]; go += gp[1536 + d];
            }
            float cp = g_c[b * Dz + d];
            float cn = sigm(gf) * cp + sigm(gi) * tanhf(gg);
            float hn = sigm(go) * tanhf(cn);
            g_c[b * Dz + d] = cn;
            g_h[b * Dz + d] = hn;
            __nv_bfloat16 hh = __float2bfloat16(hn);
            __nv_bfloat16 hl = __float2bfloat16(hn - __bfloat162float(hh));
            size_t idx = ((size_t)t * Bz + b) * Dz + d;
            g_ahi[idx] = hh;
            g_alo[idx] = hl;
            g_xhi[(size_t)b * KP + 1280 + d] = hh;
            g_xlo[(size_t)b * KP + 1280 + d] = hl;
        }
        gbar();
    }
}

// ---------------- launcher: 4 launches; #4 = gemm_fcn (ncu target) ----------------
extern "C" void kernel_launch(void* const* d_in, const int* in_sizes, int n_in,
                              void* d_out, int out_size) {
    const float* features = (const float*)d_in[0];
    const float* articles = (const float*)d_in[1];
    const int*   captions = (const int*)d_in[2];
    const float* emb      = (const float*)d_in[3];
    const float* att_W_w  = (const float*)d_in[4];
    const float* att_W_b  = (const float*)d_in[5];
    const float* att_U_w  = (const float*)d_in[6];
    const float* att_U_b  = (const float*)d_in[7];
    const float* att_A_w  = (const float*)d_in[8];
    const float* att_A_b  = (const float*)d_in[9];
    const float* pa_W_w   = (const float*)d_in[10];
    const float* pa_W_b   = (const float*)d_in[11];
    const float* pa_U_w   = (const float*)d_in[12];
    const float* pa_U_b   = (const float*)d_in[13];
    const float* pa_A_w   = (const float*)d_in[14];
    const float* pa_A_b   = (const float*)d_in[15];
    const float* init_h_w = (const float*)d_in[16];
    const float* init_h_b = (const float*)d_in[17];
    const float* init_c_w = (const float*)d_in[18];
    const float* init_c_b = (const float*)d_in[19];
    const float* lstm_w_ih = (const float*)d_in[20];
    const float* lstm_w_hh = (const float*)d_in[21];
    const float* lstm_b_ih = (const float*)d_in[22];
    const float* lstm_b_hh = (const float*)d_in[23];
    const float* fcn_w    = (const float*)d_in[24];
    const float* fcn_b    = (const float*)d_in[25];
    float* out = (float*)d_out;

    prologue<<<PB_TOTAL, 256>>>(features, articles, emb, captions,
                                init_h_w, init_h_b, init_c_w, init_c_b,
                                att_U_w, pa_U_w, lstm_w_ih, lstm_w_hh, fcn_w);
    gemm3<<<dim3(16, 146), 256>>>(att_U_b, pa_U_b);
    loop_kernel<<<NBLK, LT>>>(features, articles,
                              att_W_w, att_W_b, att_A_w, att_A_b,
                              pa_W_w, pa_W_b, pa_A_w, pa_A_b,
                              lstm_b_ih, lstm_b_hh, out);
    gemm_fcn<<<dim3(236, 16), 256>>>(fcn_b, out);
}